// round 10
// baseline (speedup 1.0000x reference)
#include <cuda_runtime.h>
#include <cuda_bf16.h>
#include <stdint.h>
#include <math.h>

#define BB   8
#define CC   512
#define CIN  256
#define HW   128
#define NN   4096
#define NHD  16
#define HD   32

__device__ float g_P1 [BB*NN*CC];
__device__ float g_P2 [BB*NN*CC];
__device__ float g_Q  [BB*NN*CC];
__device__ float g_K  [BB*NN*CC];
__device__ float g_KV [BB*NHD*HD*HD];
__device__ float g_ATT[BB*CC*NN];
__device__ float g_isc[CC];
__device__ __nv_bfloat16 g_2h[BB*CIN*HW*HW];
__device__ __nv_bfloat16 g_2l[BB*CIN*HW*HW];
__device__ __nv_bfloat16 g_wh[CC*CIN];
__device__ __nv_bfloat16 g_wl[CC*CIN];

__device__ __forceinline__ float lrelu(float x){ return x >= 0.f ? x : 0.1f*x; }

__device__ __forceinline__ uint32_t smem_u32(const void* p){
    uint32_t a;
    asm("{ .reg .u64 t; cvta.to.shared.u64 t, %1; cvt.u32.u64 %0, t; }" : "=r"(a) : "l"(p));
    return a;
}
__device__ __forceinline__ void cp16(uint32_t dst, const void* src){
    asm volatile("cp.async.cg.shared.global [%0], [%1], 16;" :: "r"(dst), "l"(src) : "memory");
}
#define CP_COMMIT()   asm volatile("cp.async.commit_group;" ::: "memory")
#define CP_WAIT(n)    asm volatile("cp.async.wait_group %0;" :: "n"(n) : "memory")

__device__ __forceinline__ void ldsm4(uint32_t* r, uint32_t addr){
    asm volatile("ldmatrix.sync.aligned.m8n8.x4.shared.b16 {%0,%1,%2,%3}, [%4];"
        : "=r"(r[0]), "=r"(r[1]), "=r"(r[2]), "=r"(r[3]) : "r"(addr));
}
__device__ __forceinline__ void ldsm4t(uint32_t* r, uint32_t addr){
    asm volatile("ldmatrix.sync.aligned.m8n8.x4.trans.shared.b16 {%0,%1,%2,%3}, [%4];"
        : "=r"(r[0]), "=r"(r[1]), "=r"(r[2]), "=r"(r[3]) : "r"(addr));
}
__device__ __forceinline__ void mma16816(float* d, const uint32_t* a, const uint32_t* b){
    asm volatile("mma.sync.aligned.m16n8k16.row.col.f32.bf16.bf16.f32 "
        "{%0,%1,%2,%3}, {%4,%5,%6,%7}, {%8,%9}, {%0,%1,%2,%3};"
        : "+f"(d[0]), "+f"(d[1]), "+f"(d[2]), "+f"(d[3])
        : "r"(a[0]), "r"(a[1]), "r"(a[2]), "r"(a[3]), "r"(b[0]), "r"(b[1]));
}

// ---------------- K0: inverse softplus scale ----------------
__global__ void k_scale(const float* __restrict__ sp){
    int c = threadIdx.x;
    float s = sp[c];
    float v = (s > 20.f) ? s : log1pf(expf(s));
    g_isc[c] = 1.f / v;
}

// ---------------- K0b/K0c: bf16 hi/lo splits ----------------
__device__ __forceinline__ void split4(float4 v, uint2* Hd, uint2* Ld){
    __nv_bfloat16 h0 = __float2bfloat16(v.x), h1 = __float2bfloat16(v.y);
    __nv_bfloat16 h2 = __float2bfloat16(v.z), h3 = __float2bfloat16(v.w);
    __nv_bfloat162 H0; H0.x = h0; H0.y = h1;
    __nv_bfloat162 H1; H1.x = h2; H1.y = h3;
    __nv_bfloat162 L0, L1;
    L0.x = __float2bfloat16(v.x - __bfloat162float(h0));
    L0.y = __float2bfloat16(v.y - __bfloat162float(h1));
    L1.x = __float2bfloat16(v.z - __bfloat162float(h2));
    L1.y = __float2bfloat16(v.w - __bfloat162float(h3));
    Hd->x = *(uint32_t*)&H0; Hd->y = *(uint32_t*)&H1;
    Ld->x = *(uint32_t*)&L0; Ld->y = *(uint32_t*)&L1;
}
__global__ void __launch_bounds__(256) k_split(const float* __restrict__ in2){
    int i = blockIdx.x*256 + threadIdx.x;     // 8 floats per thread
    float4 v0 = ((const float4*)in2)[2*i];
    float4 v1 = ((const float4*)in2)[2*i+1];
    uint4 H, L;
    split4(v0, (uint2*)&H.x, (uint2*)&L.x);
    split4(v1, (uint2*)&H.z, (uint2*)&L.z);
    ((uint4*)g_2h)[i] = H;
    ((uint4*)g_2l)[i] = L;
}
__global__ void __launch_bounds__(256) k_splitw(const float* __restrict__ w){
    int i = blockIdx.x*256 + threadIdx.x;
    float4 v0 = ((const float4*)w)[2*i];
    float4 v1 = ((const float4*)w)[2*i+1];
    uint4 H, L;
    split4(v0, (uint2*)&H.x, (uint2*)&L.x);
    split4(v1, (uint2*)&H.z, (uint2*)&L.z);
    ((uint4*)g_wh)[i] = H;
    ((uint4*)g_wl)[i] = L;
}

// ---------------- K1: 2x2 max+mean pool of input1 -> (B,N,C) ----------------
__global__ void __launch_bounds__(256) k_pool1(const float* __restrict__ in1){
    __shared__ float tile[64][65];
    int ny = blockIdx.x, c0 = blockIdx.y * 64, b = blockIdx.z;
    int tid = threadIdx.x;
    #pragma unroll
    for (int p = 0; p < 16; p++){
        int l = p*256 + tid;
        int nx = l & 63, cc = l >> 6;
        const float* base = in1 + (((b*CC + c0+cc)*HW + 2*ny)*HW + 2*nx);
        float2 r0 = *(const float2*)base;
        float2 r1 = *(const float2*)(base + HW);
        float m = fmaxf(fmaxf(r0.x, r0.y), fmaxf(r1.x, r1.y));
        float s = (r0.x + r0.y + r1.x + r1.y) * 0.25f;
        tile[cc][nx] = m + s;
    }
    __syncthreads();
    #pragma unroll
    for (int p = 0; p < 16; p++){
        int l = p*256 + tid;
        int c = l & 63, nx = l >> 6;
        g_P1[(b*NN + ny*64 + nx)*CC + c0 + c] = tile[c][nx];
    }
}

// ---------------- K2: mma.sync bf16-split GEMM + bias + 2x2 pool -> g_P2 ----------------
// CTA: 128 o x 64 px. K=256, k32 stages, 4-deep cp.async pipeline, 2 CTAs/SM.
// 8 warps = 4(wm) x 2(wn), warp tile 32x32. 3-term split: Ah*Bh + Al*Bh + Ah*Bl.
#define ASTG 16384
#define BSTG 8192
#define STAGE_SZ (ASTG + BSTG)          // 24576
#define NSTAGE 4
#define GEMM_SMEM (NSTAGE*STAGE_SZ)     // 98304

__global__ void __launch_bounds__(256, 2) k_gemm(const float* __restrict__ b_in){
    extern __shared__ char smem[];
    uint32_t sb = smem_u32(smem);
    float* Cs = (float*)smem;           // 128 x 68 f32 staging (reuses stage mem)

    int tid = threadIdx.x;
    int lane = tid & 31, wid = tid >> 5;
    int wm = wid >> 1, wn = wid & 1;
    int bid = blockIdx.x;               // ot fastest for L2 B-reuse
    int ot = bid & 3;
    int xq = (bid >> 2) & 3;
    int ny = (bid >> 4) & 63;
    int b  = bid >> 10;
    int o0 = ot * 128;

    const __nv_bfloat16* Bsrc[2] = { g_2h, g_2l };
    const __nv_bfloat16* Asrc[2] = { g_wh, g_wl };

    float acc[2][4][4];
    #pragma unroll
    for (int i = 0; i < 2; i++)
        #pragma unroll
        for (int j = 0; j < 4; j++)
            #pragma unroll
            for (int q = 0; q < 4; q++) acc[i][j][q] = 0.f;

    auto load_stage = [&](int kc){
        uint32_t st = sb + (kc & (NSTAGE-1))*STAGE_SZ;
        #pragma unroll
        for (int q = 0; q < 4; q++){            // A: 1024 x 16B
            int id = q*256 + tid;
            int sp = id >> 9, o = (id >> 2) & 127, c = id & 3;
            int cs = c ^ ((o >> 1) & 3);
            cp16(st + sp*8192 + o*64 + cs*16,
                 Asrc[sp] + (o0 + o)*CIN + kc*32 + c*8);
        }
        #pragma unroll
        for (int q = 0; q < 2; q++){            // B: 512 x 16B
            int id = q*256 + tid;
            int sp = id >> 8, k = (id >> 3) & 31, c = id & 7;
            int cs = c ^ (k & 7);
            int sy = c >> 2, x0 = (c & 3) << 3;
            cp16(st + ASTG + sp*4096 + k*128 + cs*16,
                 Bsrc[sp] + (size_t)(b*CIN + kc*32 + k)*(HW*HW)
                          + (2*ny + sy)*HW + xq*32 + x0);
        }
        CP_COMMIT();
    };

    load_stage(0);
    load_stage(1);
    load_stage(2);

    int l15 = lane & 15, lh = lane >> 4;
    int g2 = lane >> 3;
    int bk_off = (g2 & 1)*8 + (lane & 7);
    int bn_off = (g2 >> 1)*8;

    for (int kc = 0; kc < 8; kc++){
        if (kc < 6) { CP_WAIT(2); } else if (kc < 7) { CP_WAIT(1); } else { CP_WAIT(0); }
        __syncthreads();
        if (kc < 5) load_stage(kc + 3);
        uint32_t st = sb + (kc & (NSTAGE-1))*STAGE_SZ;

        #pragma unroll
        for (int ks = 0; ks < 2; ks++){
            uint32_t Ah[2][4], Al[2][4];
            #pragma unroll
            for (int mf = 0; mf < 2; mf++){
                int r = wm*32 + mf*16 + l15;
                int c = ks*2 + lh;
                int cs = c ^ ((r >> 1) & 3);
                uint32_t base = st + r*64 + cs*16;
                ldsm4(Ah[mf], base);
                ldsm4(Al[mf], base + 8192);
            }
            uint32_t Bh[2][4], Bl[2][4];
            #pragma unroll
            for (int nf2 = 0; nf2 < 2; nf2++){
                int k = ks*16 + bk_off;
                int n = wn*32 + nf2*16 + bn_off;
                int c = n >> 3;
                int cs = c ^ (k & 7);
                uint32_t base = st + ASTG + k*128 + cs*16;
                ldsm4t(Bh[nf2], base);
                ldsm4t(Bl[nf2], base + 4096);
            }
            #pragma unroll
            for (int mf = 0; mf < 2; mf++)
                #pragma unroll
                for (int nf = 0; nf < 4; nf++){
                    const uint32_t* bh = &Bh[nf >> 1][(nf & 1)*2];
                    const uint32_t* bl = &Bl[nf >> 1][(nf & 1)*2];
                    mma16816(acc[mf][nf], Ah[mf], bh);
                    mma16816(acc[mf][nf], Al[mf], bh);
                    mma16816(acc[mf][nf], Ah[mf], bl);
                }
        }
        __syncthreads();
    }

    // ---- epilogue: stage C, 2x2 pool (max + mean), +2*bias ----
    #pragma unroll
    for (int mf = 0; mf < 2; mf++)
        #pragma unroll
        for (int nf = 0; nf < 4; nf++){
            int row = wm*32 + mf*16 + (lane >> 2);
            int col = wn*32 + nf*8 + (lane & 3)*2;
            *(float2*)&Cs[row*68 + col]     = make_float2(acc[mf][nf][0], acc[mf][nf][1]);
            *(float2*)&Cs[(row+8)*68 + col] = make_float2(acc[mf][nf][2], acc[mf][nf][3]);
        }
    __syncthreads();

    int pn_base = b*NN + ny*64 + xq*16;
    #pragma unroll
    for (int j = 0; j < 8; j++){
        int idx = j*256 + tid;
        int o = idx & 127, i = idx >> 7;
        float2 v0 = *(const float2*)&Cs[o*68 + 2*i];        // sy=0
        float2 v1 = *(const float2*)&Cs[o*68 + 32 + 2*i];   // sy=1
        float m = fmaxf(fmaxf(v0.x, v0.y), fmaxf(v1.x, v1.y));
        float s = (v0.x + v0.y + v1.x + v1.y) * 0.25f;
        g_P2[(pn_base + i)*CC + o0 + o] = m + s + 2.f*b_in[o0 + o];
    }
}

// ---------------- K3: q/k = focus(lrelu(p + pos) / scale) ----------------
__global__ void __launch_bounds__(256) k_focus(const float* __restrict__ pos1,
                                               const float* __restrict__ pos2){
    int warp = threadIdx.x >> 5, lane = threadIdx.x & 31;
    int r = blockIdx.x * 8 + warp;
    int b = r >> 12, n = r & (NN - 1);
    const float* p1 = &g_P1[(b*NN + n)*CC];
    const float* p2 = &g_P2[(b*NN + n)*CC];
    const float* q1 = &pos1[n*CC];
    const float* q2 = &pos2[n*CC];
    float tq3[16], tk3[16];
    float s2q = 0.f, s6q = 0.f, s2k = 0.f, s6k = 0.f;
    #pragma unroll
    for (int i = 0; i < 4; i++){
        int c = i*128 + lane*4;
        float4 a  = *(const float4*)(p1 + c);
        float4 pa = *(const float4*)(q1 + c);
        float4 kk = *(const float4*)(p2 + c);
        float4 pk = *(const float4*)(q2 + c);
        float4 is = *(const float4*)(g_isc + c);
        float ta[4] = { lrelu(a.x + pa.x)*is.x, lrelu(a.y + pa.y)*is.y,
                        lrelu(a.z + pa.z)*is.z, lrelu(a.w + pa.w)*is.w };
        float tb[4] = { lrelu(kk.x + pk.x)*is.x, lrelu(kk.y + pk.y)*is.y,
                        lrelu(kk.z + pk.z)*is.z, lrelu(kk.w + pk.w)*is.w };
        #pragma unroll
        for (int j = 0; j < 4; j++){
            float t2 = ta[j]*ta[j]; float t3 = t2*ta[j];
            s2q += t2; s6q += t3*t3; tq3[i*4+j] = t3;
            float u2 = tb[j]*tb[j]; float u3 = u2*tb[j];
            s2k += u2; s6k += u3*u3; tk3[i*4+j] = u3;
        }
    }
    #pragma unroll
    for (int off = 16; off; off >>= 1){
        s2q += __shfl_xor_sync(0xffffffffu, s2q, off);
        s6q += __shfl_xor_sync(0xffffffffu, s6q, off);
        s2k += __shfl_xor_sync(0xffffffffu, s2k, off);
        s6k += __shfl_xor_sync(0xffffffffu, s6k, off);
    }
    float rq = sqrtf(s2q / s6q);
    float rk = sqrtf(s2k / s6k);
    #pragma unroll
    for (int i = 0; i < 4; i++){
        int c = i*128 + lane*4;
        *(float4*)&g_Q[(b*NN + n)*CC + c] =
            make_float4(rq*tq3[i*4], rq*tq3[i*4+1], rq*tq3[i*4+2], rq*tq3[i*4+3]);
        *(float4*)&g_K[(b*NN + n)*CC + c] =
            make_float4(rk*tk3[i*4], rk*tk3[i*4+1], rk*tk3[i*4+2], rk*tk3[i*4+3]);
    }
}

// ---------------- K4: kv ----------------
__global__ void __launch_bounds__(256) k_kv(){
    __shared__ float ks[64][HD];
    __shared__ float vs[64][HD];
    __shared__ float red[256*16];
    int bh = blockIdx.x;
    int b = bh >> 4, h = bh & 15;
    int tid = threadIdx.x;
    int g  = tid >> 6;
    int t6 = tid & 63;
    int ty = t6 >> 3, tx = t6 & 7;
    float acc[4][4] = {};
    const float* Kb = &g_K [(b*NN)*CC + h*HD];
    const float* Vb = &g_P2[(b*NN)*CC + h*HD];
    for (int ch = 0; ch < 64; ch++){
        #pragma unroll
        for (int p = 0; p < 8; p++){
            int l = p*256 + tid;
            int d = l & 31, nn = l >> 5;
            ks[nn][d] = Kb[(ch*64 + nn)*CC + d];
            vs[nn][d] = Vb[(ch*64 + nn)*CC + d];
        }
        __syncthreads();
        #pragma unroll
        for (int q = 0; q < 16; q++){
            int n = g*16 + q;
            float4 kk = *(const float4*)&ks[n][ty*4];
            float4 vv = *(const float4*)&vs[n][tx*4];
            float ka[4] = {kk.x, kk.y, kk.z, kk.w};
            float va[4] = {vv.x, vv.y, vv.z, vv.w};
            #pragma unroll
            for (int i = 0; i < 4; i++)
                #pragma unroll
                for (int j = 0; j < 4; j++) acc[i][j] += ka[i]*va[j];
        }
        __syncthreads();
    }
    #pragma unroll
    for (int i = 0; i < 4; i++)
        #pragma unroll
        for (int j = 0; j < 4; j++) red[tid*16 + i*4 + j] = acc[i][j];
    __syncthreads();
    if (tid < 64){
        #pragma unroll
        for (int idx = 0; idx < 16; idx++){
            float s = red[tid*16 + idx] + red[(tid+64)*16 + idx]
                    + red[(tid+128)*16 + idx] + red[(tid+192)*16 + idx];
            int i = idx >> 2, j = idx & 3;
            int d = (tid >> 3)*4 + i, e = (tid & 7)*4 + j;
            g_KV[(bh*HD + d)*HD + e] = s * (1.0f/NN);
        }
    }
}

// ---------------- K5: attn ----------------
__global__ void __launch_bounds__(256) k_attn(const float* __restrict__ w_v,
                                              const float* __restrict__ b_v){
    __shared__ float qs [128][HD];
    __shared__ float vsm[128][HD];
    __shared__ float osm[HD][128];
    int bh = blockIdx.x, seg = blockIdx.y;
    int b = bh >> 4, h = bh & 15;
    int tid = threadIdx.x;
    int e = tid & 31, grp = tid >> 5;
    float kvc[32], wv[32];
    #pragma unroll
    for (int d = 0; d < 32; d++){
        kvc[d] = g_KV[(bh*HD + d)*HD + e];
        wv[d]  = w_v[e*HD + d];
    }
    float bve = b_v[e];
    const float* Qb = &g_Q [(b*NN)*CC + h*HD];
    const float* Vb = &g_P2[(b*NN)*CC + h*HD];
    float* Ob = &g_ATT[(b*CC + h*HD)*NN];
    for (int cc = 0; cc < 8; cc++){
        int n0 = seg*1024 + cc*128;
        #pragma unroll
        for (int p = 0; p < 16; p++){
            int l = p*256 + tid;
            int d = l & 31, nn = l >> 5;
            qs [nn][d] = Qb[(n0 + nn)*CC + d];
            vsm[nn][d] = Vb[(n0 + nn)*CC + d];
        }
        __syncthreads();
        #pragma unroll
        for (int q = 0; q < 16; q++){
            int nn = grp*16 + q;
            float x = 0.f, vc = 0.f;
            #pragma unroll
            for (int d = 0; d < 32; d++){
                x  += qs [nn][d] * kvc[d];
                vc += vsm[nn][d] * wv[d];
            }
            osm[e][nn] = x + lrelu(vc + bve);
        }
        __syncthreads();
        #pragma unroll
        for (int p = 0; p < 16; p++){
            int l = p*256 + tid;
            int nn = l & 127, ee = l >> 7;
            Ob[ee*NN + n0 + nn] = osm[ee][nn];
        }
        __syncthreads();
    }
}

// ---------------- K6: bilinear upsample + sigmoid ----------------
__global__ void __launch_bounds__(256) k_upsample(float* __restrict__ out){
    int x  = threadIdx.x & 127, ys = threadIdx.x >> 7;
    int y  = blockIdx.x*2 + ys;
    int c  = blockIdx.y, b = blockIdx.z;
    const float S = 63.f / 127.f;
    float tyf = (float)y * S; int y0 = (int)tyf; if (y0 > 62) y0 = 62; float wy = tyf - (float)y0;
    float txf = (float)x * S; int x0 = (int)txf; if (x0 > 62) x0 = 62; float wx = txf - (float)x0;
    const float* att = &g_ATT[(b*CC + c)*NN];
    float a00 = att[y0*64 + x0    ], a01 = att[y0*64 + x0 + 1];
    float a10 = att[(y0+1)*64 + x0], a11 = att[(y0+1)*64 + x0 + 1];
    float r0 = a00*(1.f - wx) + a01*wx;
    float r1 = a10*(1.f - wx) + a11*wx;
    float v  = r0*(1.f - wy) + r1*wy;
    out[((b*CC + c)*HW + y)*HW + x] = 1.f / (1.f + expf(-v));
}

// ---------------- launch ----------------
extern "C" void kernel_launch(void* const* d_in, const int* in_sizes, int n_in,
                              void* d_out, int out_size){
    const float* input1 = (const float*)d_in[0];
    const float* input2 = (const float*)d_in[1];
    const float* w_in   = (const float*)d_in[2];
    const float* b_in   = (const float*)d_in[3];
    const float* w_v    = (const float*)d_in[4];
    const float* b_v    = (const float*)d_in[5];
    const float* sparam = (const float*)d_in[6];
    const float* pos1   = (const float*)d_in[7];
    const float* pos2   = (const float*)d_in[8];
    float* out = (float*)d_out;

    cudaFuncSetAttribute(k_gemm, cudaFuncAttributeMaxDynamicSharedMemorySize, GEMM_SMEM);

    // k_gemm is intentionally the 4th launch: the ncu capture window lands there.
    k_scale    <<<1, CC>>>(sparam);
    k_splitw   <<<64, 256>>>(w_in);
    k_split    <<<16384, 256>>>(input2);
    k_gemm     <<<8192, 256, GEMM_SMEM>>>(b_in);
    k_pool1    <<<dim3(64, 8, 8), 256>>>(input1);
    k_focus    <<<4096, 256>>>(pos1, pos2);
    k_kv       <<<128, 256>>>();
    k_attn     <<<dim3(128, 4), 256>>>(w_v, b_v);
    k_upsample <<<dim3(64, 512, 8), 256>>>(out);
}

// round 12
// speedup vs baseline: 1.2059x; 1.2059x over previous
#include <cuda_runtime.h>
#include <cuda_bf16.h>
#include <stdint.h>
#include <math.h>

#define BB   8
#define CC   512
#define CIN  256
#define HW   128
#define NN   4096
#define NHD  16
#define HD   32

__device__ float g_P1 [BB*NN*CC];
__device__ float g_P2 [BB*NN*CC];
__device__ float g_Q  [BB*NN*CC];
__device__ float g_K  [BB*NN*CC];
__device__ float g_KV [BB*NHD*HD*HD];
__device__ float g_KVp[8*BB*NHD*HD*HD];
__device__ float g_ATT[BB*CC*NN];
__device__ float g_isc[CC];
__device__ __nv_bfloat16 g_2h[BB*CIN*HW*HW];
__device__ __nv_bfloat16 g_2l[BB*CIN*HW*HW];
__device__ __nv_bfloat16 g_wh[CC*CIN];
__device__ __nv_bfloat16 g_wl[CC*CIN];

__device__ __forceinline__ float lrelu(float x){ return x >= 0.f ? x : 0.1f*x; }

__device__ __forceinline__ uint32_t smem_u32(const void* p){
    uint32_t a;
    asm("{ .reg .u64 t; cvta.to.shared.u64 t, %1; cvt.u32.u64 %0, t; }" : "=r"(a) : "l"(p));
    return a;
}
__device__ __forceinline__ void cp16(uint32_t dst, const void* src){
    asm volatile("cp.async.cg.shared.global [%0], [%1], 16;" :: "r"(dst), "l"(src) : "memory");
}
#define CP_COMMIT()   asm volatile("cp.async.commit_group;" ::: "memory")
#define CP_WAIT(n)    asm volatile("cp.async.wait_group %0;" :: "n"(n) : "memory")

__device__ __forceinline__ void ldsm4(uint32_t* r, uint32_t addr){
    asm volatile("ldmatrix.sync.aligned.m8n8.x4.shared.b16 {%0,%1,%2,%3}, [%4];"
        : "=r"(r[0]), "=r"(r[1]), "=r"(r[2]), "=r"(r[3]) : "r"(addr));
}
__device__ __forceinline__ void ldsm4t(uint32_t* r, uint32_t addr){
    asm volatile("ldmatrix.sync.aligned.m8n8.x4.trans.shared.b16 {%0,%1,%2,%3}, [%4];"
        : "=r"(r[0]), "=r"(r[1]), "=r"(r[2]), "=r"(r[3]) : "r"(addr));
}
__device__ __forceinline__ void mma16816(float* d, const uint32_t* a, const uint32_t* b){
    asm volatile("mma.sync.aligned.m16n8k16.row.col.f32.bf16.bf16.f32 "
        "{%0,%1,%2,%3}, {%4,%5,%6,%7}, {%8,%9}, {%0,%1,%2,%3};"
        : "+f"(d[0]), "+f"(d[1]), "+f"(d[2]), "+f"(d[3])
        : "r"(a[0]), "r"(a[1]), "r"(a[2]), "r"(a[3]), "r"(b[0]), "r"(b[1]));
}

// ---------------- K0: inverse softplus scale ----------------
__global__ void k_scale(const float* __restrict__ sp){
    int c = threadIdx.x;
    float s = sp[c];
    float v = (s > 20.f) ? s : log1pf(expf(s));
    g_isc[c] = 1.f / v;
}

// ---------------- K0b/K0c: bf16 hi/lo splits ----------------
__device__ __forceinline__ void split4(float4 v, uint2* Hd, uint2* Ld){
    __nv_bfloat16 h0 = __float2bfloat16(v.x), h1 = __float2bfloat16(v.y);
    __nv_bfloat16 h2 = __float2bfloat16(v.z), h3 = __float2bfloat16(v.w);
    __nv_bfloat162 H0; H0.x = h0; H0.y = h1;
    __nv_bfloat162 H1; H1.x = h2; H1.y = h3;
    __nv_bfloat162 L0, L1;
    L0.x = __float2bfloat16(v.x - __bfloat162float(h0));
    L0.y = __float2bfloat16(v.y - __bfloat162float(h1));
    L1.x = __float2bfloat16(v.z - __bfloat162float(h2));
    L1.y = __float2bfloat16(v.w - __bfloat162float(h3));
    Hd->x = *(uint32_t*)&H0; Hd->y = *(uint32_t*)&H1;
    Ld->x = *(uint32_t*)&L0; Ld->y = *(uint32_t*)&L1;
}
__global__ void __launch_bounds__(256) k_split(const float* __restrict__ in2){
    int i = blockIdx.x*256 + threadIdx.x;
    float4 v0 = ((const float4*)in2)[2*i];
    float4 v1 = ((const float4*)in2)[2*i+1];
    uint4 H, L;
    split4(v0, (uint2*)&H.x, (uint2*)&L.x);
    split4(v1, (uint2*)&H.z, (uint2*)&L.z);
    ((uint4*)g_2h)[i] = H;
    ((uint4*)g_2l)[i] = L;
}
__global__ void __launch_bounds__(256) k_splitw(const float* __restrict__ w){
    int i = blockIdx.x*256 + threadIdx.x;
    float4 v0 = ((const float4*)w)[2*i];
    float4 v1 = ((const float4*)w)[2*i+1];
    uint4 H, L;
    split4(v0, (uint2*)&H.x, (uint2*)&L.x);
    split4(v1, (uint2*)&H.z, (uint2*)&L.z);
    ((uint4*)g_wh)[i] = H;
    ((uint4*)g_wl)[i] = L;
}

// ---------------- K1: 2x2 max+mean pool of input1 -> (B,N,C) ----------------
__global__ void __launch_bounds__(256) k_pool1(const float* __restrict__ in1){
    __shared__ float tile[64][65];
    int ny = blockIdx.x, c0 = blockIdx.y * 64, b = blockIdx.z;
    int tid = threadIdx.x;
    #pragma unroll
    for (int p = 0; p < 16; p++){
        int l = p*256 + tid;
        int nx = l & 63, cc = l >> 6;
        const float* base = in1 + (((b*CC + c0+cc)*HW + 2*ny)*HW + 2*nx);
        float2 r0 = *(const float2*)base;
        float2 r1 = *(const float2*)(base + HW);
        float m = fmaxf(fmaxf(r0.x, r0.y), fmaxf(r1.x, r1.y));
        float s = (r0.x + r0.y + r1.x + r1.y) * 0.25f;
        tile[cc][nx] = m + s;
    }
    __syncthreads();
    #pragma unroll
    for (int p = 0; p < 16; p++){
        int l = p*256 + tid;
        int c = l & 63, nx = l >> 6;
        g_P1[(b*NN + ny*64 + nx)*CC + c0 + c] = tile[c][nx];
    }
}

// ---------------- K2: mma.sync bf16-split GEMM + bias + 2x2 pool -> g_P2 ----------------
#define ASTG 16384
#define BSTG 8192
#define STAGE_SZ (ASTG + BSTG)          // 24576
#define GEMM_SMEM (3*STAGE_SZ)          // 73728

__global__ void __launch_bounds__(256, 2) k_gemm(const float* __restrict__ b_in){
    extern __shared__ char smem[];
    uint32_t sb = smem_u32(smem);
    float* Cs = (float*)smem;           // 128 x 68 f32 staging (reuses stage mem)

    int tid = threadIdx.x;
    int lane = tid & 31, wid = tid >> 5;
    int wm = wid >> 1, wn = wid & 1;
    int bid = blockIdx.x;               // ot fastest for L2 B-reuse
    int ot = bid & 3;
    int xq = (bid >> 2) & 3;
    int ny = (bid >> 4) & 63;
    int b  = bid >> 10;
    int o0 = ot * 128;

    const __nv_bfloat16* Bsrc[2] = { g_2h, g_2l };
    const __nv_bfloat16* Asrc[2] = { g_wh, g_wl };

    float acc[2][4][4];
    #pragma unroll
    for (int i = 0; i < 2; i++)
        #pragma unroll
        for (int j = 0; j < 4; j++)
            #pragma unroll
            for (int q = 0; q < 4; q++) acc[i][j][q] = 0.f;

    auto load_stage = [&](int kc){
        uint32_t st = sb + (kc % 3)*STAGE_SZ;
        #pragma unroll
        for (int q = 0; q < 4; q++){            // A: 1024 x 16B
            int id = q*256 + tid;
            int sp = id >> 9, o = (id >> 2) & 127, c = id & 3;
            int cs = c ^ ((o >> 1) & 3);
            cp16(st + sp*8192 + o*64 + cs*16,
                 Asrc[sp] + (o0 + o)*CIN + kc*32 + c*8);
        }
        #pragma unroll
        for (int q = 0; q < 2; q++){            // B: 512 x 16B
            int id = q*256 + tid;
            int sp = id >> 8, k = (id >> 3) & 31, c = id & 7;
            int cs = c ^ (k & 7);
            int sy = c >> 2, x0 = (c & 3) << 3;
            cp16(st + ASTG + sp*4096 + k*128 + cs*16,
                 Bsrc[sp] + (size_t)(b*CIN + kc*32 + k)*(HW*HW)
                          + (2*ny + sy)*HW + xq*32 + x0);
        }
        CP_COMMIT();
    };

    load_stage(0);
    load_stage(1);

    int l15 = lane & 15, lh = lane >> 4;
    int g2 = lane >> 3;
    int bk_off = (g2 & 1)*8 + (lane & 7);
    int bn_off = (g2 >> 1)*8;

    for (int kc = 0; kc < 8; kc++){
        if (kc < 7) { CP_WAIT(1); } else { CP_WAIT(0); }
        __syncthreads();
        if (kc < 6) load_stage(kc + 2);
        uint32_t st = sb + (kc % 3)*STAGE_SZ;

        #pragma unroll
        for (int ks = 0; ks < 2; ks++){
            uint32_t Ah[2][4], Al[2][4];
            #pragma unroll
            for (int mf = 0; mf < 2; mf++){
                int r = wm*32 + mf*16 + l15;
                int c = ks*2 + lh;
                int cs = c ^ ((r >> 1) & 3);
                uint32_t base = st + r*64 + cs*16;
                ldsm4(Ah[mf], base);
                ldsm4(Al[mf], base + 8192);
            }
            uint32_t Bh[2][4], Bl[2][4];
            #pragma unroll
            for (int nf2 = 0; nf2 < 2; nf2++){
                int k = ks*16 + bk_off;
                int n = wn*32 + nf2*16 + bn_off;
                int c = n >> 3;
                int cs = c ^ (k & 7);
                uint32_t base = st + ASTG + k*128 + cs*16;
                ldsm4t(Bh[nf2], base);
                ldsm4t(Bl[nf2], base + 4096);
            }
            #pragma unroll
            for (int mf = 0; mf < 2; mf++)
                #pragma unroll
                for (int nf = 0; nf < 4; nf++){
                    const uint32_t* bh = &Bh[nf >> 1][(nf & 1)*2];
                    const uint32_t* bl = &Bl[nf >> 1][(nf & 1)*2];
                    mma16816(acc[mf][nf], Ah[mf], bh);
                    mma16816(acc[mf][nf], Al[mf], bh);
                    mma16816(acc[mf][nf], Ah[mf], bl);
                }
        }
        __syncthreads();
    }

    // ---- epilogue: stage C, 2x2 pool (max + mean), +2*bias ----
    #pragma unroll
    for (int mf = 0; mf < 2; mf++)
        #pragma unroll
        for (int nf = 0; nf < 4; nf++){
            int row = wm*32 + mf*16 + (lane >> 2);
            int col = wn*32 + nf*8 + (lane & 3)*2;
            *(float2*)&Cs[row*68 + col]     = make_float2(acc[mf][nf][0], acc[mf][nf][1]);
            *(float2*)&Cs[(row+8)*68 + col] = make_float2(acc[mf][nf][2], acc[mf][nf][3]);
        }
    __syncthreads();

    int pn_base = b*NN + ny*64 + xq*16;
    #pragma unroll
    for (int j = 0; j < 8; j++){
        int idx = j*256 + tid;
        int o = idx & 127, i = idx >> 7;
        float2 v0 = *(const float2*)&Cs[o*68 + 2*i];        // sy=0
        float2 v1 = *(const float2*)&Cs[o*68 + 32 + 2*i];   // sy=1
        float m = fmaxf(fmaxf(v0.x, v0.y), fmaxf(v1.x, v1.y));
        float s = (v0.x + v0.y + v1.x + v1.y) * 0.25f;
        g_P2[(pn_base + i)*CC + o0 + o] = m + s + 2.f*b_in[o0 + o];
    }
}

// ---------------- K3: q/k = focus(lrelu(p + pos) / scale) ----------------
__global__ void __launch_bounds__(256) k_focus(const float* __restrict__ pos1,
                                               const float* __restrict__ pos2){
    int warp = threadIdx.x >> 5, lane = threadIdx.x & 31;
    int r = blockIdx.x * 8 + warp;
    int b = r >> 12, n = r & (NN - 1);
    const float* p1 = &g_P1[(b*NN + n)*CC];
    const float* p2 = &g_P2[(b*NN + n)*CC];
    const float* q1 = &pos1[n*CC];
    const float* q2 = &pos2[n*CC];
    float tq3[16], tk3[16];
    float s2q = 0.f, s6q = 0.f, s2k = 0.f, s6k = 0.f;
    #pragma unroll
    for (int i = 0; i < 4; i++){
        int c = i*128 + lane*4;
        float4 a  = *(const float4*)(p1 + c);
        float4 pa = *(const float4*)(q1 + c);
        float4 kk = *(const float4*)(p2 + c);
        float4 pk = *(const float4*)(q2 + c);
        float4 is = *(const float4*)(g_isc + c);
        float ta[4] = { lrelu(a.x + pa.x)*is.x, lrelu(a.y + pa.y)*is.y,
                        lrelu(a.z + pa.z)*is.z, lrelu(a.w + pa.w)*is.w };
        float tb[4] = { lrelu(kk.x + pk.x)*is.x, lrelu(kk.y + pk.y)*is.y,
                        lrelu(kk.z + pk.z)*is.z, lrelu(kk.w + pk.w)*is.w };
        #pragma unroll
        for (int j = 0; j < 4; j++){
            float t2 = ta[j]*ta[j]; float t3 = t2*ta[j];
            s2q += t2; s6q += t3*t3; tq3[i*4+j] = t3;
            float u2 = tb[j]*tb[j]; float u3 = u2*tb[j];
            s2k += u2; s6k += u3*u3; tk3[i*4+j] = u3;
        }
    }
    #pragma unroll
    for (int off = 16; off; off >>= 1){
        s2q += __shfl_xor_sync(0xffffffffu, s2q, off);
        s6q += __shfl_xor_sync(0xffffffffu, s6q, off);
        s2k += __shfl_xor_sync(0xffffffffu, s2k, off);
        s6k += __shfl_xor_sync(0xffffffffu, s6k, off);
    }
    float rq = sqrtf(s2q / s6q);
    float rk = sqrtf(s2k / s6k);
    #pragma unroll
    for (int i = 0; i < 4; i++){
        int c = i*128 + lane*4;
        *(float4*)&g_Q[(b*NN + n)*CC + c] =
            make_float4(rq*tq3[i*4], rq*tq3[i*4+1], rq*tq3[i*4+2], rq*tq3[i*4+3]);
        *(float4*)&g_K[(b*NN + n)*CC + c] =
            make_float4(rk*tk3[i*4], rk*tk3[i*4+1], rk*tk3[i*4+2], rk*tk3[i*4+3]);
    }
}

// ---------------- K4a: partial kv over 1/8 of N (1024 CTAs) ----------------
__global__ void __launch_bounds__(256) k_kvp(){
    __shared__ float ks[64][HD];
    __shared__ float vs[64][HD];
    __shared__ float red[256*16];
    int bh  = blockIdx.x & 127;
    int seg = blockIdx.x >> 7;
    int b = bh >> 4, h = bh & 15;
    int tid = threadIdx.x;
    int g  = tid >> 6;
    int t6 = tid & 63;
    int ty = t6 >> 3, tx = t6 & 7;
    float acc[4][4] = {};
    const float* Kb = &g_K [(b*NN)*CC + h*HD];
    const float* Vb = &g_P2[(b*NN)*CC + h*HD];
    for (int ch = seg*8; ch < seg*8 + 8; ch++){
        #pragma unroll
        for (int p = 0; p < 8; p++){
            int l = p*256 + tid;
            int d = l & 31, nn = l >> 5;
            ks[nn][d] = Kb[(ch*64 + nn)*CC + d];
            vs[nn][d] = Vb[(ch*64 + nn)*CC + d];
        }
        __syncthreads();
        #pragma unroll
        for (int q = 0; q < 16; q++){
            int n = g*16 + q;
            float4 kk = *(const float4*)&ks[n][ty*4];
            float4 vv = *(const float4*)&vs[n][tx*4];
            float ka[4] = {kk.x, kk.y, kk.z, kk.w};
            float va[4] = {vv.x, vv.y, vv.z, vv.w};
            #pragma unroll
            for (int i = 0; i < 4; i++)
                #pragma unroll
                for (int j = 0; j < 4; j++) acc[i][j] += ka[i]*va[j];
        }
        __syncthreads();
    }
    #pragma unroll
    for (int i = 0; i < 4; i++)
        #pragma unroll
        for (int j = 0; j < 4; j++) red[tid*16 + i*4 + j] = acc[i][j];
    __syncthreads();
    if (tid < 64){
        #pragma unroll
        for (int idx = 0; idx < 16; idx++){
            float s = red[tid*16 + idx] + red[(tid+64)*16 + idx]
                    + red[(tid+128)*16 + idx] + red[(tid+192)*16 + idx];
            int i = idx >> 2, j = idx & 3;
            int d = (tid >> 3)*4 + i, e = (tid & 7)*4 + j;
            g_KVp[(seg*128 + bh)*1024 + d*HD + e] = s;
        }
    }
}

// ---------------- K4b: reduce 8 partials -> g_KV ----------------
__global__ void __launch_bounds__(1024) k_kvr(){
    int bh = blockIdx.x, idx = threadIdx.x;
    float s = 0.f;
    #pragma unroll
    for (int g = 0; g < 8; g++) s += g_KVp[(g*128 + bh)*1024 + idx];
    g_KV[bh*1024 + idx] = s * (1.0f/NN);
}

// ---------------- K5: attn = q@kv + lrelu(v@wv^T + bv) -> (B,C,N) ----------------
__global__ void __launch_bounds__(256) k_attn(const float* __restrict__ w_v,
                                              const float* __restrict__ b_v){
    __shared__ float qs [128][HD];
    __shared__ float vsm[128][HD];
    __shared__ float osm[HD][132];      // padded: kills 32-way bank conflict on [e][nn]
    int bh = blockIdx.x, seg = blockIdx.y;
    int b = bh >> 4, h = bh & 15;
    int tid = threadIdx.x;
    int e = tid & 31, grp = tid >> 5;
    float kvc[32], wv[32];
    #pragma unroll
    for (int d = 0; d < 32; d++){
        kvc[d] = g_KV[(bh*HD + d)*HD + e];
        wv[d]  = w_v[e*HD + d];
    }
    float bve = b_v[e];
    const float* Qb = &g_Q [(b*NN)*CC + h*HD];
    const float* Vb = &g_P2[(b*NN)*CC + h*HD];
    float* Ob = &g_ATT[(b*CC + h*HD)*NN];
    for (int cc = 0; cc < 8; cc++){
        int n0 = seg*1024 + cc*128;
        #pragma unroll
        for (int p = 0; p < 16; p++){
            int l = p*256 + tid;
            int d = l & 31, nn = l >> 5;
            qs [nn][d] = Qb[(n0 + nn)*CC + d];
            vsm[nn][d] = Vb[(n0 + nn)*CC + d];
        }
        __syncthreads();
        #pragma unroll
        for (int q = 0; q < 16; q++){
            int nn = grp*16 + q;
            float x = 0.f, vc = 0.f;
            #pragma unroll
            for (int d4 = 0; d4 < 8; d4++){
                float4 qv = *(const float4*)&qs [nn][d4*4];
                float4 vv = *(const float4*)&vsm[nn][d4*4];
                x  += qv.x*kvc[d4*4] + qv.y*kvc[d4*4+1] + qv.z*kvc[d4*4+2] + qv.w*kvc[d4*4+3];
                vc += vv.x*wv [d4*4] + vv.y*wv [d4*4+1] + vv.z*wv [d4*4+2] + vv.w*wv [d4*4+3];
            }
            osm[e][nn] = x + lrelu(vc + bve);
        }
        __syncthreads();
        #pragma unroll
        for (int p = 0; p < 16; p++){
            int l = p*256 + tid;
            int nn = l & 127, ee = l >> 7;
            Ob[ee*NN + n0 + nn] = osm[ee][nn];
        }
        __syncthreads();
    }
}

// ---------------- K6: bilinear upsample + sigmoid ----------------
__global__ void __launch_bounds__(256) k_upsample(float* __restrict__ out){
    int x  = threadIdx.x & 127, ys = threadIdx.x >> 7;
    int y  = blockIdx.x*2 + ys;
    int c  = blockIdx.y, b = blockIdx.z;
    const float S = 63.f / 127.f;
    float tyf = (float)y * S; int y0 = (int)tyf; if (y0 > 62) y0 = 62; float wy = tyf - (float)y0;
    float txf = (float)x * S; int x0 = (int)txf; if (x0 > 62) x0 = 62; float wx = txf - (float)x0;
    const float* att = &g_ATT[(b*CC + c)*NN];
    float a00 = att[y0*64 + x0    ], a01 = att[y0*64 + x0 + 1];
    float a10 = att[(y0+1)*64 + x0], a11 = att[(y0+1)*64 + x0 + 1];
    float r0 = a00*(1.f - wx) + a01*wx;
    float r1 = a10*(1.f - wx) + a11*wx;
    float v  = r0*(1.f - wy) + r1*wy;
    out[((b*CC + c)*HW + y)*HW + x] = 1.f / (1.f + expf(-v));
}

// ---------------- launch ----------------
extern "C" void kernel_launch(void* const* d_in, const int* in_sizes, int n_in,
                              void* d_out, int out_size){
    const float* input1 = (const float*)d_in[0];
    const float* input2 = (const float*)d_in[1];
    const float* w_in   = (const float*)d_in[2];
    const float* b_in   = (const float*)d_in[3];
    const float* w_v    = (const float*)d_in[4];
    const float* b_v    = (const float*)d_in[5];
    const float* sparam = (const float*)d_in[6];
    const float* pos1   = (const float*)d_in[7];
    const float* pos2   = (const float*)d_in[8];
    float* out = (float*)d_out;

    cudaFuncSetAttribute(k_gemm, cudaFuncAttributeMaxDynamicSharedMemorySize, GEMM_SMEM);

    // k_gemm stays the 4th launch: the ncu capture window lands there.
    k_scale    <<<1, CC>>>(sparam);
    k_splitw   <<<64, 256>>>(w_in);
    k_split    <<<16384, 256>>>(input2);
    k_gemm     <<<8192, 256, GEMM_SMEM>>>(b_in);
    k_pool1    <<<dim3(64, 8, 8), 256>>>(input1);
    k_focus    <<<4096, 256>>>(pos1, pos2);
    k_kvp      <<<1024, 256>>>();
    k_kvr      <<<128, 1024>>>();
    k_attn     <<<dim3(128, 4), 256>>>(w_v, b_v);
    k_upsample <<<dim3(64, 512, 8), 256>>>(out);
}

// round 13
// speedup vs baseline: 1.3156x; 1.0910x over previous
#include <cuda_runtime.h>
#include <cuda_bf16.h>
#include <stdint.h>
#include <math.h>

#define BB   8
#define CC   512
#define CIN  256
#define HW   128
#define NN   4096
#define NHD  16
#define HD   32

__device__ float g_P1 [BB*NN*CC];
__device__ float g_P2 [BB*NN*CC];
__device__ float g_Q  [BB*NN*CC];
__device__ float g_K  [BB*NN*CC];
__device__ float g_KV [BB*NHD*HD*HD];
__device__ float g_KVp[8*BB*NHD*HD*HD];
__device__ float g_ATT[BB*CC*NN];
__device__ float g_isc[CC];
__device__ __nv_bfloat16 g_2h[BB*CIN*HW*HW];
__device__ __nv_bfloat16 g_wh[CC*CIN];
__device__ __nv_bfloat16 g_wl[CC*CIN];

__device__ __forceinline__ float lrelu(float x){ return x >= 0.f ? x : 0.1f*x; }

__device__ __forceinline__ uint32_t smem_u32(const void* p){
    uint32_t a;
    asm("{ .reg .u64 t; cvta.to.shared.u64 t, %1; cvt.u32.u64 %0, t; }" : "=r"(a) : "l"(p));
    return a;
}
__device__ __forceinline__ void cp16(uint32_t dst, const void* src){
    asm volatile("cp.async.cg.shared.global [%0], [%1], 16;" :: "r"(dst), "l"(src) : "memory");
}
#define CP_COMMIT()   asm volatile("cp.async.commit_group;" ::: "memory")
#define CP_WAIT(n)    asm volatile("cp.async.wait_group %0;" :: "n"(n) : "memory")

__device__ __forceinline__ void ldsm4(uint32_t* r, uint32_t addr){
    asm volatile("ldmatrix.sync.aligned.m8n8.x4.shared.b16 {%0,%1,%2,%3}, [%4];"
        : "=r"(r[0]), "=r"(r[1]), "=r"(r[2]), "=r"(r[3]) : "r"(addr));
}
__device__ __forceinline__ void ldsm4t(uint32_t* r, uint32_t addr){
    asm volatile("ldmatrix.sync.aligned.m8n8.x4.trans.shared.b16 {%0,%1,%2,%3}, [%4];"
        : "=r"(r[0]), "=r"(r[1]), "=r"(r[2]), "=r"(r[3]) : "r"(addr));
}
__device__ __forceinline__ void mma16816(float* d, const uint32_t* a, const uint32_t* b){
    asm volatile("mma.sync.aligned.m16n8k16.row.col.f32.bf16.bf16.f32 "
        "{%0,%1,%2,%3}, {%4,%5,%6,%7}, {%8,%9}, {%0,%1,%2,%3};"
        : "+f"(d[0]), "+f"(d[1]), "+f"(d[2]), "+f"(d[3])
        : "r"(a[0]), "r"(a[1]), "r"(a[2]), "r"(a[3]), "r"(b[0]), "r"(b[1]));
}

// ---------------- K0: inverse softplus scale ----------------
__global__ void k_scale(const float* __restrict__ sp){
    int c = threadIdx.x;
    float s = sp[c];
    float v = (s > 20.f) ? s : log1pf(expf(s));
    g_isc[c] = 1.f / v;
}

// ---------------- K0b: bf16 convert of input2 (hi only) ----------------
__global__ void __launch_bounds__(256) k_split(const float* __restrict__ in2){
    int i = blockIdx.x*256 + threadIdx.x;      // 8 floats/thread
    float4 v0 = ((const float4*)in2)[2*i];
    float4 v1 = ((const float4*)in2)[2*i+1];
    __nv_bfloat162 a; a.x = __float2bfloat16(v0.x); a.y = __float2bfloat16(v0.y);
    __nv_bfloat162 b; b.x = __float2bfloat16(v0.z); b.y = __float2bfloat16(v0.w);
    __nv_bfloat162 c; c.x = __float2bfloat16(v1.x); c.y = __float2bfloat16(v1.y);
    __nv_bfloat162 d; d.x = __float2bfloat16(v1.z); d.y = __float2bfloat16(v1.w);
    uint4 H;
    H.x = *(uint32_t*)&a; H.y = *(uint32_t*)&b;
    H.z = *(uint32_t*)&c; H.w = *(uint32_t*)&d;
    ((uint4*)g_2h)[i] = H;
}

// ---------------- K0c: bf16 hi/lo split of w_in ----------------
__device__ __forceinline__ void split4(float4 v, uint2* Hd, uint2* Ld){
    __nv_bfloat16 h0 = __float2bfloat16(v.x), h1 = __float2bfloat16(v.y);
    __nv_bfloat16 h2 = __float2bfloat16(v.z), h3 = __float2bfloat16(v.w);
    __nv_bfloat162 H0; H0.x = h0; H0.y = h1;
    __nv_bfloat162 H1; H1.x = h2; H1.y = h3;
    __nv_bfloat162 L0, L1;
    L0.x = __float2bfloat16(v.x - __bfloat162float(h0));
    L0.y = __float2bfloat16(v.y - __bfloat162float(h1));
    L1.x = __float2bfloat16(v.z - __bfloat162float(h2));
    L1.y = __float2bfloat16(v.w - __bfloat162float(h3));
    Hd->x = *(uint32_t*)&H0; Hd->y = *(uint32_t*)&H1;
    Ld->x = *(uint32_t*)&L0; Ld->y = *(uint32_t*)&L1;
}
__global__ void __launch_bounds__(256) k_splitw(const float* __restrict__ w){
    int i = blockIdx.x*256 + threadIdx.x;
    float4 v0 = ((const float4*)w)[2*i];
    float4 v1 = ((const float4*)w)[2*i+1];
    uint4 H, L;
    split4(v0, (uint2*)&H.x, (uint2*)&L.x);
    split4(v1, (uint2*)&H.z, (uint2*)&L.z);
    ((uint4*)g_wh)[i] = H;
    ((uint4*)g_wl)[i] = L;
}

// ---------------- K1: 2x2 max+mean pool of input1 -> (B,N,C) ----------------
__global__ void __launch_bounds__(256) k_pool1(const float* __restrict__ in1){
    __shared__ float tile[64][65];
    int ny = blockIdx.x, c0 = blockIdx.y * 64, b = blockIdx.z;
    int tid = threadIdx.x;
    #pragma unroll
    for (int p = 0; p < 16; p++){
        int l = p*256 + tid;
        int nx = l & 63, cc = l >> 6;
        const float* base = in1 + (((b*CC + c0+cc)*HW + 2*ny)*HW + 2*nx);
        float2 r0 = *(const float2*)base;
        float2 r1 = *(const float2*)(base + HW);
        float m = fmaxf(fmaxf(r0.x, r0.y), fmaxf(r1.x, r1.y));
        float s = (r0.x + r0.y + r1.x + r1.y) * 0.25f;
        tile[cc][nx] = m + s;
    }
    __syncthreads();
    #pragma unroll
    for (int p = 0; p < 16; p++){
        int l = p*256 + tid;
        int c = l & 63, nx = l >> 6;
        g_P1[(b*NN + ny*64 + nx)*CC + c0 + c] = tile[c][nx];
    }
}

// ---------------- K2: mma.sync 2-term GEMM + bias + 2x2 pool -> g_P2 ----------------
// A = w_in split hi+lo (exact to ~16 mantissa bits); B = input2 single bf16.
// D = Ah*Bh + Al*Bh. CTA: 128 o x 64 px, k32 stages, 3-deep pipeline, 2 CTAs/SM.
#define ASTG 16384
#define BSTG 4096
#define STAGE_SZ (ASTG + BSTG)          // 20480
#define GEMM_SMEM (3*STAGE_SZ)          // 61440 (>= 128*68*4 C staging)

__global__ void __launch_bounds__(256, 2) k_gemm(const float* __restrict__ b_in){
    extern __shared__ char smem[];
    uint32_t sb = smem_u32(smem);
    float* Cs = (float*)smem;

    int tid = threadIdx.x;
    int lane = tid & 31, wid = tid >> 5;
    int wm = wid >> 1, wn = wid & 1;
    int bid = blockIdx.x;               // ot fastest for L2 B-reuse
    int ot = bid & 3;
    int xq = (bid >> 2) & 3;
    int ny = (bid >> 4) & 63;
    int b  = bid >> 10;
    int o0 = ot * 128;

    const __nv_bfloat16* Asrc[2] = { g_wh, g_wl };

    float acc[2][4][4];
    #pragma unroll
    for (int i = 0; i < 2; i++)
        #pragma unroll
        for (int j = 0; j < 4; j++)
            #pragma unroll
            for (int q = 0; q < 4; q++) acc[i][j][q] = 0.f;

    auto load_stage = [&](int kc){
        uint32_t st = sb + (kc % 3)*STAGE_SZ;
        #pragma unroll
        for (int q = 0; q < 4; q++){            // A: 1024 x 16B (hi+lo)
            int id = q*256 + tid;
            int sp = id >> 9, o = (id >> 2) & 127, c = id & 3;
            int cs = c ^ ((o >> 1) & 3);
            cp16(st + sp*8192 + o*64 + cs*16,
                 Asrc[sp] + (o0 + o)*CIN + kc*32 + c*8);
        }
        {                                        // B: 256 x 16B (hi only)
            int id = tid;
            int k = (id >> 3) & 31, c = id & 7;
            int cs = c ^ (k & 7);
            int sy = c >> 2, x0 = (c & 3) << 3;
            cp16(st + ASTG + k*128 + cs*16,
                 g_2h + (size_t)(b*CIN + kc*32 + k)*(HW*HW)
                      + (2*ny + sy)*HW + xq*32 + x0);
        }
        CP_COMMIT();
    };

    load_stage(0);
    load_stage(1);

    int l15 = lane & 15, lh = lane >> 4;
    int g2 = lane >> 3;
    int bk_off = (g2 & 1)*8 + (lane & 7);
    int bn_off = (g2 >> 1)*8;

    for (int kc = 0; kc < 8; kc++){
        if (kc < 7) { CP_WAIT(1); } else { CP_WAIT(0); }
        __syncthreads();
        if (kc < 6) load_stage(kc + 2);
        uint32_t st = sb + (kc % 3)*STAGE_SZ;

        #pragma unroll
        for (int ks = 0; ks < 2; ks++){
            uint32_t Ah[2][4], Al[2][4];
            #pragma unroll
            for (int mf = 0; mf < 2; mf++){
                int r = wm*32 + mf*16 + l15;
                int c = ks*2 + lh;
                int cs = c ^ ((r >> 1) & 3);
                uint32_t base = st + r*64 + cs*16;
                ldsm4(Ah[mf], base);
                ldsm4(Al[mf], base + 8192);
            }
            uint32_t Bh[2][4];
            #pragma unroll
            for (int nf2 = 0; nf2 < 2; nf2++){
                int k = ks*16 + bk_off;
                int n = wn*32 + nf2*16 + bn_off;
                int c = n >> 3;
                int cs = c ^ (k & 7);
                ldsm4t(Bh[nf2], st + ASTG + k*128 + cs*16);
            }
            #pragma unroll
            for (int mf = 0; mf < 2; mf++)
                #pragma unroll
                for (int nf = 0; nf < 4; nf++){
                    const uint32_t* bh = &Bh[nf >> 1][(nf & 1)*2];
                    mma16816(acc[mf][nf], Ah[mf], bh);
                    mma16816(acc[mf][nf], Al[mf], bh);
                }
        }
        __syncthreads();
    }

    // ---- epilogue: stage C, 2x2 pool (max + mean), +2*bias ----
    #pragma unroll
    for (int mf = 0; mf < 2; mf++)
        #pragma unroll
        for (int nf = 0; nf < 4; nf++){
            int row = wm*32 + mf*16 + (lane >> 2);
            int col = wn*32 + nf*8 + (lane & 3)*2;
            *(float2*)&Cs[row*68 + col]     = make_float2(acc[mf][nf][0], acc[mf][nf][1]);
            *(float2*)&Cs[(row+8)*68 + col] = make_float2(acc[mf][nf][2], acc[mf][nf][3]);
        }
    __syncthreads();

    int pn_base = b*NN + ny*64 + xq*16;
    #pragma unroll
    for (int j = 0; j < 8; j++){
        int idx = j*256 + tid;
        int o = idx & 127, i = idx >> 7;
        float2 v0 = *(const float2*)&Cs[o*68 + 2*i];        // sy=0
        float2 v1 = *(const float2*)&Cs[o*68 + 32 + 2*i];   // sy=1
        float m = fmaxf(fmaxf(v0.x, v0.y), fmaxf(v1.x, v1.y));
        float s = (v0.x + v0.y + v1.x + v1.y) * 0.25f;
        g_P2[(pn_base + i)*CC + o0 + o] = m + s + 2.f*b_in[o0 + o];
    }
}

// ---------------- K3: q/k = focus(lrelu(p + pos) / scale) ----------------
__global__ void __launch_bounds__(256) k_focus(const float* __restrict__ pos1,
                                               const float* __restrict__ pos2){
    int warp = threadIdx.x >> 5, lane = threadIdx.x & 31;
    int r = blockIdx.x * 8 + warp;
    int b = r >> 12, n = r & (NN - 1);
    const float* p1 = &g_P1[(b*NN + n)*CC];
    const float* p2 = &g_P2[(b*NN + n)*CC];
    const float* q1 = &pos1[n*CC];
    const float* q2 = &pos2[n*CC];
    float tq3[16], tk3[16];
    float s2q = 0.f, s6q = 0.f, s2k = 0.f, s6k = 0.f;
    #pragma unroll
    for (int i = 0; i < 4; i++){
        int c = i*128 + lane*4;
        float4 a  = *(const float4*)(p1 + c);
        float4 pa = *(const float4*)(q1 + c);
        float4 kk = *(const float4*)(p2 + c);
        float4 pk = *(const float4*)(q2 + c);
        float4 is = *(const float4*)(g_isc + c);
        float ta[4] = { lrelu(a.x + pa.x)*is.x, lrelu(a.y + pa.y)*is.y,
                        lrelu(a.z + pa.z)*is.z, lrelu(a.w + pa.w)*is.w };
        float tb[4] = { lrelu(kk.x + pk.x)*is.x, lrelu(kk.y + pk.y)*is.y,
                        lrelu(kk.z + pk.z)*is.z, lrelu(kk.w + pk.w)*is.w };
        #pragma unroll
        for (int j = 0; j < 4; j++){
            float t2 = ta[j]*ta[j]; float t3 = t2*ta[j];
            s2q += t2; s6q += t3*t3; tq3[i*4+j] = t3;
            float u2 = tb[j]*tb[j]; float u3 = u2*tb[j];
            s2k += u2; s6k += u3*u3; tk3[i*4+j] = u3;
        }
    }
    #pragma unroll
    for (int off = 16; off; off >>= 1){
        s2q += __shfl_xor_sync(0xffffffffu, s2q, off);
        s6q += __shfl_xor_sync(0xffffffffu, s6q, off);
        s2k += __shfl_xor_sync(0xffffffffu, s2k, off);
        s6k += __shfl_xor_sync(0xffffffffu, s6k, off);
    }
    float rq = sqrtf(s2q / s6q);
    float rk = sqrtf(s2k / s6k);
    #pragma unroll
    for (int i = 0; i < 4; i++){
        int c = i*128 + lane*4;
        *(float4*)&g_Q[(b*NN + n)*CC + c] =
            make_float4(rq*tq3[i*4], rq*tq3[i*4+1], rq*tq3[i*4+2], rq*tq3[i*4+3]);
        *(float4*)&g_K[(b*NN + n)*CC + c] =
            make_float4(rk*tk3[i*4], rk*tk3[i*4+1], rk*tk3[i*4+2], rk*tk3[i*4+3]);
    }
}

// ---------------- K4a: partial kv over 1/8 of N ----------------
__global__ void __launch_bounds__(256) k_kvp(){
    __shared__ float ks[64][HD];
    __shared__ float vs[64][HD];
    __shared__ float red[256*16];
    int bh  = blockIdx.x & 127;
    int seg = blockIdx.x >> 7;
    int b = bh >> 4, h = bh & 15;
    int tid = threadIdx.x;
    int g  = tid >> 6;
    int t6 = tid & 63;
    int ty = t6 >> 3, tx = t6 & 7;
    float acc[4][4] = {};
    const float* Kb = &g_K [(b*NN)*CC + h*HD];
    const float* Vb = &g_P2[(b*NN)*CC + h*HD];
    for (int ch = seg*8; ch < seg*8 + 8; ch++){
        #pragma unroll
        for (int p = 0; p < 8; p++){
            int l = p*256 + tid;
            int d = l & 31, nn = l >> 5;
            ks[nn][d] = Kb[(ch*64 + nn)*CC + d];
            vs[nn][d] = Vb[(ch*64 + nn)*CC + d];
        }
        __syncthreads();
        #pragma unroll
        for (int q = 0; q < 16; q++){
            int n = g*16 + q;
            float4 kk = *(const float4*)&ks[n][ty*4];
            float4 vv = *(const float4*)&vs[n][tx*4];
            float ka[4] = {kk.x, kk.y, kk.z, kk.w};
            float va[4] = {vv.x, vv.y, vv.z, vv.w};
            #pragma unroll
            for (int i = 0; i < 4; i++)
                #pragma unroll
                for (int j = 0; j < 4; j++) acc[i][j] += ka[i]*va[j];
        }
        __syncthreads();
    }
    #pragma unroll
    for (int i = 0; i < 4; i++)
        #pragma unroll
        for (int j = 0; j < 4; j++) red[tid*16 + i*4 + j] = acc[i][j];
    __syncthreads();
    if (tid < 64){
        #pragma unroll
        for (int idx = 0; idx < 16; idx++){
            float s = red[tid*16 + idx] + red[(tid+64)*16 + idx]
                    + red[(tid+128)*16 + idx] + red[(tid+192)*16 + idx];
            int i = idx >> 2, j = idx & 3;
            int d = (tid >> 3)*4 + i, e = (tid & 7)*4 + j;
            g_KVp[(seg*128 + bh)*1024 + d*HD + e] = s;
        }
    }
}

// ---------------- K4b: reduce partials -> g_KV ----------------
__global__ void __launch_bounds__(1024) k_kvr(){
    int bh = blockIdx.x, idx = threadIdx.x;
    float s = 0.f;
    #pragma unroll
    for (int g = 0; g < 8; g++) s += g_KVp[(g*128 + bh)*1024 + idx];
    g_KV[bh*1024 + idx] = s * (1.0f/NN);
}

// ---------------- K5: attn = q@kv + lrelu(v@wv^T + bv) -> (B,C,N) ----------------
__global__ void __launch_bounds__(256) k_attn(const float* __restrict__ w_v,
                                              const float* __restrict__ b_v){
    __shared__ float qs [128][HD];
    __shared__ float vsm[128][HD];
    __shared__ float osm[HD][132];
    int bh = blockIdx.x, seg = blockIdx.y;
    int b = bh >> 4, h = bh & 15;
    int tid = threadIdx.x;
    int e = tid & 31, grp = tid >> 5;
    float kvc[32], wv[32];
    #pragma unroll
    for (int d = 0; d < 32; d++){
        kvc[d] = g_KV[(bh*HD + d)*HD + e];
        wv[d]  = w_v[e*HD + d];
    }
    float bve = b_v[e];
    const float* Qb = &g_Q [(b*NN)*CC + h*HD];
    const float* Vb = &g_P2[(b*NN)*CC + h*HD];
    float* Ob = &g_ATT[(b*CC + h*HD)*NN];
    for (int cc = 0; cc < 8; cc++){
        int n0 = seg*1024 + cc*128;
        #pragma unroll
        for (int p = 0; p < 16; p++){
            int l = p*256 + tid;
            int d = l & 31, nn = l >> 5;
            qs [nn][d] = Qb[(n0 + nn)*CC + d];
            vsm[nn][d] = Vb[(n0 + nn)*CC + d];
        }
        __syncthreads();
        #pragma unroll
        for (int q = 0; q < 16; q++){
            int nn = grp*16 + q;
            float x = 0.f, vc = 0.f;
            #pragma unroll
            for (int d4 = 0; d4 < 8; d4++){
                float4 qv = *(const float4*)&qs [nn][d4*4];
                float4 vv = *(const float4*)&vsm[nn][d4*4];
                x  += qv.x*kvc[d4*4] + qv.y*kvc[d4*4+1] + qv.z*kvc[d4*4+2] + qv.w*kvc[d4*4+3];
                vc += vv.x*wv [d4*4] + vv.y*wv [d4*4+1] + vv.z*wv [d4*4+2] + vv.w*wv [d4*4+3];
            }
            osm[e][nn] = x + lrelu(vc + bve);
        }
        __syncthreads();
        #pragma unroll
        for (int p = 0; p < 16; p++){
            int l = p*256 + tid;
            int nn = l & 127, ee = l >> 7;
            Ob[ee*NN + n0 + nn] = osm[ee][nn];
        }
        __syncthreads();
    }
}

// ---------------- K6: bilinear upsample + sigmoid ----------------
__global__ void __launch_bounds__(256) k_upsample(float* __restrict__ out){
    int x  = threadIdx.x & 127, ys = threadIdx.x >> 7;
    int y  = blockIdx.x*2 + ys;
    int c  = blockIdx.y, b = blockIdx.z;
    const float S = 63.f / 127.f;
    float tyf = (float)y * S; int y0 = (int)tyf; if (y0 > 62) y0 = 62; float wy = tyf - (float)y0;
    float txf = (float)x * S; int x0 = (int)txf; if (x0 > 62) x0 = 62; float wx = txf - (float)x0;
    const float* att = &g_ATT[(b*CC + c)*NN];
    float a00 = att[y0*64 + x0    ], a01 = att[y0*64 + x0 + 1];
    float a10 = att[(y0+1)*64 + x0], a11 = att[(y0+1)*64 + x0 + 1];
    float r0 = a00*(1.f - wx) + a01*wx;
    float r1 = a10*(1.f - wx) + a11*wx;
    float v  = r0*(1.f - wy) + r1*wy;
    out[((b*CC + c)*HW + y)*HW + x] = 1.f / (1.f + expf(-v));
}

// ---------------- launch ----------------
extern "C" void kernel_launch(void* const* d_in, const int* in_sizes, int n_in,
                              void* d_out, int out_size){
    const float* input1 = (const float*)d_in[0];
    const float* input2 = (const float*)d_in[1];
    const float* w_in   = (const float*)d_in[2];
    const float* b_in   = (const float*)d_in[3];
    const float* w_v    = (const float*)d_in[4];
    const float* b_v    = (const float*)d_in[5];
    const float* sparam = (const float*)d_in[6];
    const float* pos1   = (const float*)d_in[7];
    const float* pos2   = (const float*)d_in[8];
    float* out = (float*)d_out;

    cudaFuncSetAttribute(k_gemm, cudaFuncAttributeMaxDynamicSharedMemorySize, GEMM_SMEM);

    // k_gemm stays the 4th launch: the ncu capture window lands there.
    k_scale    <<<1, CC>>>(sparam);
    k_splitw   <<<64, 256>>>(w_in);
    k_split    <<<16384, 256>>>(input2);
    k_gemm     <<<8192, 256, GEMM_SMEM>>>(b_in);
    k_pool1    <<<dim3(64, 8, 8), 256>>>(input1);
    k_focus    <<<4096, 256>>>(pos1, pos2);
    k_kvp      <<<1024, 256>>>();
    k_kvr      <<<128, 1024>>>();
    k_attn     <<<dim3(128, 4), 256>>>(w_v, b_v);
    k_upsample <<<dim3(64, 512, 8), 256>>>(out);
}

// round 15
// speedup vs baseline: 1.3759x; 1.0459x over previous
#include <cuda_runtime.h>
#include <cuda_bf16.h>
#include <stdint.h>
#include <math.h>

#define BB   8
#define CC   512
#define CIN  256
#define HW   128
#define NN   4096
#define NHD  16
#define HD   32

__device__ float g_P1 [BB*NN*CC];
__device__ float g_P2 [BB*NN*CC];
__device__ float g_Q  [BB*NN*CC];
__device__ float g_K  [BB*NN*CC];
__device__ float g_KV [BB*NHD*HD*HD];
__device__ float g_KVp[8*BB*NHD*HD*HD];
__device__ float g_ATT[BB*CC*NN];
__device__ float g_isc[CC];
__device__ __nv_bfloat16 g_2h[BB*CIN*HW*HW];
__device__ __nv_bfloat16 g_wh[CC*CIN];
__device__ __nv_bfloat16 g_wl[CC*CIN];

__device__ __forceinline__ float lrelu(float x){ return x >= 0.f ? x : 0.1f*x; }

__device__ __forceinline__ uint32_t smem_u32(const void* p){
    uint32_t a;
    asm("{ .reg .u64 t; cvta.to.shared.u64 t, %1; cvt.u32.u64 %0, t; }" : "=r"(a) : "l"(p));
    return a;
}
__device__ __forceinline__ void cp16(uint32_t dst, const void* src){
    asm volatile("cp.async.cg.shared.global [%0], [%1], 16;" :: "r"(dst), "l"(src) : "memory");
}
#define CP_COMMIT()   asm volatile("cp.async.commit_group;" ::: "memory")
#define CP_WAIT(n)    asm volatile("cp.async.wait_group %0;" :: "n"(n) : "memory")

__device__ __forceinline__ void ldsm4(uint32_t* r, uint32_t addr){
    asm volatile("ldmatrix.sync.aligned.m8n8.x4.shared.b16 {%0,%1,%2,%3}, [%4];"
        : "=r"(r[0]), "=r"(r[1]), "=r"(r[2]), "=r"(r[3]) : "r"(addr));
}
__device__ __forceinline__ void ldsm4t(uint32_t* r, uint32_t addr){
    asm volatile("ldmatrix.sync.aligned.m8n8.x4.trans.shared.b16 {%0,%1,%2,%3}, [%4];"
        : "=r"(r[0]), "=r"(r[1]), "=r"(r[2]), "=r"(r[3]) : "r"(addr));
}
__device__ __forceinline__ void mma16816(float* d, const uint32_t* a, const uint32_t* b){
    asm volatile("mma.sync.aligned.m16n8k16.row.col.f32.bf16.bf16.f32 "
        "{%0,%1,%2,%3}, {%4,%5,%6,%7}, {%8,%9}, {%0,%1,%2,%3};"
        : "+f"(d[0]), "+f"(d[1]), "+f"(d[2]), "+f"(d[3])
        : "r"(a[0]), "r"(a[1]), "r"(a[2]), "r"(a[3]), "r"(b[0]), "r"(b[1]));
}
__device__ __forceinline__ uint32_t bf2pack(float x, float y){
    __nv_bfloat162 t; t.x = __float2bfloat16(x); t.y = __float2bfloat16(y);
    return *(uint32_t*)&t;
}

// ---------------- K0: inverse softplus scale ----------------
__global__ void k_scale(const float* __restrict__ sp){
    int c = threadIdx.x;
    float s = sp[c];
    float v = (s > 20.f) ? s : log1pf(expf(s));
    g_isc[c] = 1.f / v;
}

// ---------------- K0b: bf16 convert of input2 ----------------
__global__ void __launch_bounds__(256) k_split(const float* __restrict__ in2){
    int i = blockIdx.x*256 + threadIdx.x;
    float4 v0 = ((const float4*)in2)[2*i];
    float4 v1 = ((const float4*)in2)[2*i+1];
    uint4 H;
    H.x = bf2pack(v0.x, v0.y); H.y = bf2pack(v0.z, v0.w);
    H.z = bf2pack(v1.x, v1.y); H.w = bf2pack(v1.z, v1.w);
    ((uint4*)g_2h)[i] = H;
}

// ---------------- K0c: bf16 hi/lo split of w_in ----------------
__device__ __forceinline__ void split4(float4 v, uint2* Hd, uint2* Ld){
    __nv_bfloat16 h0 = __float2bfloat16(v.x), h1 = __float2bfloat16(v.y);
    __nv_bfloat16 h2 = __float2bfloat16(v.z), h3 = __float2bfloat16(v.w);
    __nv_bfloat162 H0; H0.x = h0; H0.y = h1;
    __nv_bfloat162 H1; H1.x = h2; H1.y = h3;
    __nv_bfloat162 L0, L1;
    L0.x = __float2bfloat16(v.x - __bfloat162float(h0));
    L0.y = __float2bfloat16(v.y - __bfloat162float(h1));
    L1.x = __float2bfloat16(v.z - __bfloat162float(h2));
    L1.y = __float2bfloat16(v.w - __bfloat162float(h3));
    Hd->x = *(uint32_t*)&H0; Hd->y = *(uint32_t*)&H1;
    Ld->x = *(uint32_t*)&L0; Ld->y = *(uint32_t*)&L1;
}
__global__ void __launch_bounds__(256) k_splitw(const float* __restrict__ w){
    int i = blockIdx.x*256 + threadIdx.x;
    float4 v0 = ((const float4*)w)[2*i];
    float4 v1 = ((const float4*)w)[2*i+1];
    uint4 H, L;
    split4(v0, (uint2*)&H.x, (uint2*)&L.x);
    split4(v1, (uint2*)&H.z, (uint2*)&L.z);
    ((uint4*)g_wh)[i] = H;
    ((uint4*)g_wl)[i] = L;
}

// ---------------- K1: 2x2 max+mean pool of input1 -> (B,N,C) ----------------
__global__ void __launch_bounds__(256) k_pool1(const float* __restrict__ in1){
    __shared__ float tile[64][65];
    int ny = blockIdx.x, c0 = blockIdx.y * 64, b = blockIdx.z;
    int tid = threadIdx.x;
    #pragma unroll
    for (int p = 0; p < 16; p++){
        int l = p*256 + tid;
        int nx = l & 63, cc = l >> 6;
        const float* base = in1 + (((b*CC + c0+cc)*HW + 2*ny)*HW + 2*nx);
        float2 r0 = *(const float2*)base;
        float2 r1 = *(const float2*)(base + HW);
        float m = fmaxf(fmaxf(r0.x, r0.y), fmaxf(r1.x, r1.y));
        float s = (r0.x + r0.y + r1.x + r1.y) * 0.25f;
        tile[cc][nx] = m + s;
    }
    __syncthreads();
    #pragma unroll
    for (int p = 0; p < 16; p++){
        int l = p*256 + tid;
        int c = l & 63, nx = l >> 6;
        g_P1[(b*NN + ny*64 + nx)*CC + c0 + c] = tile[c][nx];
    }
}

// ---------------- K2: mma.sync 2-term GEMM + bias + 2x2 pool -> g_P2 ----------------
// CTA: 128 o x 128 px (2 sy x 64 x). Warp tile 32x64 (4m x 2n warps).
// A = w_in hi+lo (64B rows, chunk^((o>>1)&3)); B = input2 bf16 (256B rows, chunk^(k&7)).
// D = Ah*Bh + Al*Bh. 3-stage pipeline, 2 CTAs/SM.
#define ASTG 16384
#define BSTG 8192
#define STAGE_SZ (ASTG + BSTG)          // 24576
#define GEMM_SMEM (3*STAGE_SZ)          // 73728 (>= 128*132*4 C staging)

__global__ void __launch_bounds__(256, 2) k_gemm(const float* __restrict__ b_in){
    extern __shared__ char smem[];
    uint32_t sb = smem_u32(smem);
    float* Cs = (float*)smem;

    int tid = threadIdx.x;
    int lane = tid & 31, wid = tid >> 5;
    int wm = wid >> 1, wn = wid & 1;    // 4m x 2n warps
    int bid = blockIdx.x;               // ot fastest for L2 B-reuse
    int ot = bid & 3;
    int xh = (bid >> 2) & 1;
    int ny = (bid >> 3) & 63;
    int b  = bid >> 9;
    int o0 = ot * 128;

    const __nv_bfloat16* Asrc[2] = { g_wh, g_wl };

    float acc[2][8][4];
    #pragma unroll
    for (int i = 0; i < 2; i++)
        #pragma unroll
        for (int j = 0; j < 8; j++)
            #pragma unroll
            for (int q = 0; q < 4; q++) acc[i][j][q] = 0.f;

    auto load_stage = [&](int kc){
        uint32_t st = sb + (kc % 3)*STAGE_SZ;
        #pragma unroll
        for (int q = 0; q < 4; q++){            // A: 1024 x 16B (hi+lo)
            int id = q*256 + tid;
            int sp = id >> 9, o = (id >> 2) & 127, c = id & 3;
            int cs = c ^ ((o >> 1) & 3);
            cp16(st + sp*8192 + o*64 + cs*16,
                 Asrc[sp] + (o0 + o)*CIN + kc*32 + c*8);
        }
        #pragma unroll
        for (int q = 0; q < 2; q++){            // B: 512 x 16B, rows 256B
            int id = q*256 + tid;
            int k = id >> 4, c = id & 15;
            int cs = c ^ (k & 7);
            int sy = c >> 3, x0 = (c & 7) << 3;
            cp16(st + ASTG + k*256 + cs*16,
                 g_2h + (size_t)(b*CIN + kc*32 + k)*(HW*HW)
                      + (2*ny + sy)*HW + xh*64 + x0);
        }
        CP_COMMIT();
    };

    load_stage(0);
    load_stage(1);

    int l15 = lane & 15, lh = lane >> 4;
    int g2 = lane >> 3;
    int bk_off = (g2 & 1)*8 + (lane & 7);
    int bn_off = (g2 >> 1)*8;

    for (int kc = 0; kc < 8; kc++){
        if (kc < 7) { CP_WAIT(1); } else { CP_WAIT(0); }
        __syncthreads();
        if (kc < 6) load_stage(kc + 2);
        uint32_t st = sb + (kc % 3)*STAGE_SZ;

        #pragma unroll
        for (int ks = 0; ks < 2; ks++){
            uint32_t Ah[2][4], Al[2][4];
            #pragma unroll
            for (int mf = 0; mf < 2; mf++){
                int r = wm*32 + mf*16 + l15;
                int c = ks*2 + lh;
                int cs = c ^ ((r >> 1) & 3);
                uint32_t base = st + r*64 + cs*16;
                ldsm4(Ah[mf], base);
                ldsm4(Al[mf], base + 8192);
            }
            uint32_t Bh[4][4];
            #pragma unroll
            for (int nf2 = 0; nf2 < 4; nf2++){
                int k = ks*16 + bk_off;
                int n = wn*64 + nf2*16 + bn_off;
                int c = n >> 3;
                int cs = c ^ (k & 7);
                ldsm4t(Bh[nf2], st + ASTG + k*256 + cs*16);
            }
            #pragma unroll
            for (int mf = 0; mf < 2; mf++)
                #pragma unroll
                for (int nf = 0; nf < 8; nf++){
                    const uint32_t* bh = &Bh[nf >> 1][(nf & 1)*2];
                    mma16816(acc[mf][nf], Ah[mf], bh);
                    mma16816(acc[mf][nf], Al[mf], bh);
                }
        }
        __syncthreads();
    }

    // ---- epilogue: stage C (128 x 132), 2x2 pool (max + mean), +2*bias ----
    #pragma unroll
    for (int mf = 0; mf < 2; mf++)
        #pragma unroll
        for (int nf = 0; nf < 8; nf++){
            int row = wm*32 + mf*16 + (lane >> 2);
            int col = wn*64 + nf*8 + (lane & 3)*2;
            *(float2*)&Cs[row*132 + col]     = make_float2(acc[mf][nf][0], acc[mf][nf][1]);
            *(float2*)&Cs[(row+8)*132 + col] = make_float2(acc[mf][nf][2], acc[mf][nf][3]);
        }
    __syncthreads();

    int pn_base = b*NN + ny*64 + xh*32;
    #pragma unroll
    for (int j = 0; j < 16; j++){
        int idx = j*256 + tid;
        int o = idx & 127, i = idx >> 7;        // pooled px i 0..31
        float2 v0 = *(const float2*)&Cs[o*132 + 2*i];        // sy=0
        float2 v1 = *(const float2*)&Cs[o*132 + 64 + 2*i];   // sy=1
        float m = fmaxf(fmaxf(v0.x, v0.y), fmaxf(v1.x, v1.y));
        float s = (v0.x + v0.y + v1.x + v1.y) * 0.25f;
        g_P2[(pn_base + i)*CC + o0 + o] = m + s + 2.f*b_in[o0 + o];
    }
}

// ---------------- K3: q/k = focus(lrelu(p + pos) / scale) ----------------
__global__ void __launch_bounds__(256) k_focus(const float* __restrict__ pos1,
                                               const float* __restrict__ pos2){
    int warp = threadIdx.x >> 5, lane = threadIdx.x & 31;
    int r = blockIdx.x * 8 + warp;
    int b = r >> 12, n = r & (NN - 1);
    const float* p1 = &g_P1[(b*NN + n)*CC];
    const float* p2 = &g_P2[(b*NN + n)*CC];
    const float* q1 = &pos1[n*CC];
    const float* q2 = &pos2[n*CC];
    float tq3[16], tk3[16];
    float s2q = 0.f, s6q = 0.f, s2k = 0.f, s6k = 0.f;
    #pragma unroll
    for (int i = 0; i < 4; i++){
        int c = i*128 + lane*4;
        float4 a  = *(const float4*)(p1 + c);
        float4 pa = *(const float4*)(q1 + c);
        float4 kk = *(const float4*)(p2 + c);
        float4 pk = *(const float4*)(q2 + c);
        float4 is = *(const float4*)(g_isc + c);
        float ta[4] = { lrelu(a.x + pa.x)*is.x, lrelu(a.y + pa.y)*is.y,
                        lrelu(a.z + pa.z)*is.z, lrelu(a.w + pa.w)*is.w };
        float tb[4] = { lrelu(kk.x + pk.x)*is.x, lrelu(kk.y + pk.y)*is.y,
                        lrelu(kk.z + pk.z)*is.z, lrelu(kk.w + pk.w)*is.w };
        #pragma unroll
        for (int j = 0; j < 4; j++){
            float t2 = ta[j]*ta[j]; float t3 = t2*ta[j];
            s2q += t2; s6q += t3*t3; tq3[i*4+j] = t3;
            float u2 = tb[j]*tb[j]; float u3 = u2*tb[j];
            s2k += u2; s6k += u3*u3; tk3[i*4+j] = u3;
        }
    }
    #pragma unroll
    for (int off = 16; off; off >>= 1){
        s2q += __shfl_xor_sync(0xffffffffu, s2q, off);
        s6q += __shfl_xor_sync(0xffffffffu, s6q, off);
        s2k += __shfl_xor_sync(0xffffffffu, s2k, off);
        s6k += __shfl_xor_sync(0xffffffffu, s6k, off);
    }
    float rq = sqrtf(s2q / s6q);
    float rk = sqrtf(s2k / s6k);
    #pragma unroll
    for (int i = 0; i < 4; i++){
        int c = i*128 + lane*4;
        *(float4*)&g_Q[(b*NN + n)*CC + c] =
            make_float4(rq*tq3[i*4], rq*tq3[i*4+1], rq*tq3[i*4+2], rq*tq3[i*4+3]);
        *(float4*)&g_K[(b*NN + n)*CC + c] =
            make_float4(rk*tk3[i*4], rk*tk3[i*4+1], rk*tk3[i*4+2], rk*tk3[i*4+3]);
    }
}

// ---------------- K4a: partial kv over 1/8 of N ----------------
__global__ void __launch_bounds__(256) k_kvp(){
    __shared__ float ks[64][HD];
    __shared__ float vs[64][HD];
    __shared__ float red[256*16];
    int bh  = blockIdx.x & 127;
    int seg = blockIdx.x >> 7;
    int b = bh >> 4, h = bh & 15;
    int tid = threadIdx.x;
    int g  = tid >> 6;
    int t6 = tid & 63;
    int ty = t6 >> 3, tx = t6 & 7;
    float acc[4][4] = {};
    const float* Kb = &g_K [(b*NN)*CC + h*HD];
    const float* Vb = &g_P2[(b*NN)*CC + h*HD];
    for (int ch = seg*8; ch < seg*8 + 8; ch++){
        #pragma unroll
        for (int p = 0; p < 8; p++){
            int l = p*256 + tid;
            int d = l & 31, nn = l >> 5;
            ks[nn][d] = Kb[(ch*64 + nn)*CC + d];
            vs[nn][d] = Vb[(ch*64 + nn)*CC + d];
        }
        __syncthreads();
        #pragma unroll
        for (int q = 0; q < 16; q++){
            int n = g*16 + q;
            float4 kk = *(const float4*)&ks[n][ty*4];
            float4 vv = *(const float4*)&vs[n][tx*4];
            float ka[4] = {kk.x, kk.y, kk.z, kk.w};
            float va[4] = {vv.x, vv.y, vv.z, vv.w};
            #pragma unroll
            for (int i = 0; i < 4; i++)
                #pragma unroll
                for (int j = 0; j < 4; j++) acc[i][j] += ka[i]*va[j];
        }
        __syncthreads();
    }
    #pragma unroll
    for (int i = 0; i < 4; i++)
        #pragma unroll
        for (int j = 0; j < 4; j++) red[tid*16 + i*4 + j] = acc[i][j];
    __syncthreads();
    if (tid < 64){
        #pragma unroll
        for (int idx = 0; idx < 16; idx++){
            float s = red[tid*16 + idx] + red[(tid+64)*16 + idx]
                    + red[(tid+128)*16 + idx] + red[(tid+192)*16 + idx];
            int i = idx >> 2, j = idx & 3;
            int d = (tid >> 3)*4 + i, e = (tid & 7)*4 + j;
            g_KVp[(seg*128 + bh)*1024 + d*HD + e] = s;
        }
    }
}

// ---------------- K4b: reduce partials -> g_KV ----------------
__global__ void __launch_bounds__(1024) k_kvr(){
    int bh = blockIdx.x, idx = threadIdx.x;
    float s = 0.f;
    #pragma unroll
    for (int g = 0; g < 8; g++) s += g_KVp[(g*128 + bh)*1024 + idx];
    g_KV[bh*1024 + idx] = s * (1.0f/NN);
}

// ---------------- K5: attn = q@kv + lrelu(v@wv^T + bv) -> (B,C,N) ----------------
__global__ void __launch_bounds__(256) k_attn(const float* __restrict__ w_v,
                                              const float* __restrict__ b_v){
    __shared__ float qs [128][HD];
    __shared__ float vsm[128][HD];
    __shared__ float osm[HD][132];
    int bh = blockIdx.x, seg = blockIdx.y;
    int b = bh >> 4, h = bh & 15;
    int tid = threadIdx.x;
    int e = tid & 31, grp = tid >> 5;
    float kvc[32], wv[32];
    #pragma unroll
    for (int d = 0; d < 32; d++){
        kvc[d] = g_KV[(bh*HD + d)*HD + e];
        wv[d]  = w_v[e*HD + d];
    }
    float bve = b_v[e];
    const float* Qb = &g_Q [(b*NN)*CC + h*HD];
    const float* Vb = &g_P2[(b*NN)*CC + h*HD];
    float* Ob = &g_ATT[(b*CC + h*HD)*NN];
    for (int cc = 0; cc < 8; cc++){
        int n0 = seg*1024 + cc*128;
        #pragma unroll
        for (int p = 0; p < 16; p++){
            int l = p*256 + tid;
            int d = l & 31, nn = l >> 5;
            qs [nn][d] = Qb[(n0 + nn)*CC + d];
            vsm[nn][d] = Vb[(n0 + nn)*CC + d];
        }
        __syncthreads();
        #pragma unroll
        for (int q = 0; q < 16; q++){
            int nn = grp*16 + q;
            float x = 0.f, vc = 0.f;
            #pragma unroll
            for (int d4 = 0; d4 < 8; d4++){
                float4 qv = *(const float4*)&qs [nn][d4*4];
                float4 vv = *(const float4*)&vsm[nn][d4*4];
                x  += qv.x*kvc[d4*4] + qv.y*kvc[d4*4+1] + qv.z*kvc[d4*4+2] + qv.w*kvc[d4*4+3];
                vc += vv.x*wv [d4*4] + vv.y*wv [d4*4+1] + vv.z*wv [d4*4+2] + vv.w*wv [d4*4+3];
            }
            osm[e][nn] = x + lrelu(vc + bve);
        }
        __syncthreads();
        #pragma unroll
        for (int p = 0; p < 16; p++){
            int l = p*256 + tid;
            int nn = l & 127, ee = l >> 7;
            Ob[ee*NN + n0 + nn] = osm[ee][nn];
        }
        __syncthreads();
    }
}

// ---------------- K6: bilinear upsample + sigmoid ----------------
__global__ void __launch_bounds__(256) k_upsample(float* __restrict__ out){
    int x  = threadIdx.x & 127, ys = threadIdx.x >> 7;
    int y  = blockIdx.x*2 + ys;
    int c  = blockIdx.y, b = blockIdx.z;
    const float S = 63.f / 127.f;
    float tyf = (float)y * S; int y0 = (int)tyf; if (y0 > 62) y0 = 62; float wy = tyf - (float)y0;
    float txf = (float)x * S; int x0 = (int)txf; if (x0 > 62) x0 = 62; float wx = txf - (float)x0;
    const float* att = &g_ATT[(b*CC + c)*NN];
    float a00 = att[y0*64 + x0    ], a01 = att[y0*64 + x0 + 1];
    float a10 = att[(y0+1)*64 + x0], a11 = att[(y0+1)*64 + x0 + 1];
    float r0 = a00*(1.f - wx) + a01*wx;
    float r1 = a10*(1.f - wx) + a11*wx;
    float v  = r0*(1.f - wy) + r1*wy;
    out[((b*CC + c)*HW + y)*HW + x] = 1.f / (1.f + expf(-v));
}

// ---------------- launch ----------------
extern "C" void kernel_launch(void* const* d_in, const int* in_sizes, int n_in,
                              void* d_out, int out_size){
    const float* input1 = (const float*)d_in[0];
    const float* input2 = (const float*)d_in[1];
    const float* w_in   = (const float*)d_in[2];
    const float* b_in   = (const float*)d_in[3];
    const float* w_v    = (const float*)d_in[4];
    const float* b_v    = (const float*)d_in[5];
    const float* sparam = (const float*)d_in[6];
    const float* pos1   = (const float*)d_in[7];
    const float* pos2   = (const float*)d_in[8];
    float* out = (float*)d_out;

    cudaFuncSetAttribute(k_gemm, cudaFuncAttributeMaxDynamicSharedMemorySize, GEMM_SMEM);

    // k_gemm stays the 4th launch: the ncu capture window lands there.
    k_scale    <<<1, CC>>>(sparam);
    k_splitw   <<<64, 256>>>(w_in);
    k_split    <<<16384, 256>>>(input2);
    k_gemm     <<<4096, 256, GEMM_SMEM>>>(b_in);
    k_pool1    <<<dim3(64, 8, 8), 256>>>(input1);
    k_focus    <<<4096, 256>>>(pos1, pos2);
    k_kvp      <<<1024, 256>>>();
    k_kvr      <<<128, 1024>>>();
    k_attn     <<<dim3(128, 4), 256>>>(w_v, b_v);
    k_upsample <<<dim3(64, 512, 8), 256>>>(out);
}

// round 16
// speedup vs baseline: 1.4161x; 1.0292x over previous
#include <cuda_runtime.h>
#include <cuda_bf16.h>
#include <stdint.h>
#include <math.h>

#define BB   8
#define CC   512
#define CIN  256
#define HW   128
#define NN   4096
#define NHD  16
#define HD   32

typedef unsigned long long ull;

__device__ float g_P1 [BB*NN*CC];
__device__ float g_P2 [BB*NN*CC];
__device__ float g_Q  [BB*NN*CC];
__device__ float g_K  [BB*NN*CC];
__device__ float g_KV [BB*NHD*HD*HD];
__device__ float g_KVp[8*BB*NHD*HD*HD];
__device__ float g_ATT[BB*CC*NN];
__device__ float g_isc[CC];
__device__ __nv_bfloat16 g_2h[BB*CIN*HW*HW];
__device__ __nv_bfloat16 g_wh[CC*CIN];

__device__ __forceinline__ float lrelu(float x){ return x >= 0.f ? x : 0.1f*x; }

__device__ __forceinline__ uint32_t smem_u32(const void* p){
    uint32_t a;
    asm("{ .reg .u64 t; cvta.to.shared.u64 t, %1; cvt.u32.u64 %0, t; }" : "=r"(a) : "l"(p));
    return a;
}
__device__ __forceinline__ void cp16(uint32_t dst, const void* src){
    asm volatile("cp.async.cg.shared.global [%0], [%1], 16;" :: "r"(dst), "l"(src) : "memory");
}
#define CP_COMMIT()   asm volatile("cp.async.commit_group;" ::: "memory")
#define CP_WAIT(n)    asm volatile("cp.async.wait_group %0;" :: "n"(n) : "memory")

__device__ __forceinline__ void ldsm4(uint32_t* r, uint32_t addr){
    asm volatile("ldmatrix.sync.aligned.m8n8.x4.shared.b16 {%0,%1,%2,%3}, [%4];"
        : "=r"(r[0]), "=r"(r[1]), "=r"(r[2]), "=r"(r[3]) : "r"(addr));
}
__device__ __forceinline__ void ldsm4t(uint32_t* r, uint32_t addr){
    asm volatile("ldmatrix.sync.aligned.m8n8.x4.trans.shared.b16 {%0,%1,%2,%3}, [%4];"
        : "=r"(r[0]), "=r"(r[1]), "=r"(r[2]), "=r"(r[3]) : "r"(addr));
}
__device__ __forceinline__ void mma16816(float* d, const uint32_t* a, const uint32_t* b){
    asm volatile("mma.sync.aligned.m16n8k16.row.col.f32.bf16.bf16.f32 "
        "{%0,%1,%2,%3}, {%4,%5,%6,%7}, {%8,%9}, {%0,%1,%2,%3};"
        : "+f"(d[0]), "+f"(d[1]), "+f"(d[2]), "+f"(d[3])
        : "r"(a[0]), "r"(a[1]), "r"(a[2]), "r"(a[3]), "r"(b[0]), "r"(b[1]));
}
__device__ __forceinline__ uint32_t bf2pack(float x, float y){
    __nv_bfloat162 t; t.x = __float2bfloat16(x); t.y = __float2bfloat16(y);
    return *(uint32_t*)&t;
}
__device__ __forceinline__ ull ffma2(ull a, ull b, ull c){
    ull d;
    asm("fma.rn.f32x2 %0, %1, %2, %3;" : "=l"(d) : "l"(a), "l"(b), "l"(c));
    return d;
}
__device__ __forceinline__ ull pack2(float x, float y){
    ull r; asm("mov.b64 %0, {%1,%2};" : "=l"(r) : "f"(x), "f"(y)); return r;
}
__device__ __forceinline__ void unpack2(ull v, float &x, float &y){
    asm("mov.b64 {%0,%1}, %2;" : "=f"(x), "=f"(y) : "l"(v));
}

// ---------------- K0: inverse softplus scale ----------------
__global__ void k_scale(const float* __restrict__ sp){
    int c = threadIdx.x;
    float s = sp[c];
    float v = (s > 20.f) ? s : log1pf(expf(s));
    g_isc[c] = 1.f / v;
}

// ---------------- K0b: bf16 convert of input2 ----------------
__global__ void __launch_bounds__(256) k_split(const float* __restrict__ in2){
    int i = blockIdx.x*256 + threadIdx.x;
    float4 v0 = ((const float4*)in2)[2*i];
    float4 v1 = ((const float4*)in2)[2*i+1];
    uint4 H;
    H.x = bf2pack(v0.x, v0.y); H.y = bf2pack(v0.z, v0.w);
    H.z = bf2pack(v1.x, v1.y); H.w = bf2pack(v1.z, v1.w);
    ((uint4*)g_2h)[i] = H;
}

// ---------------- K0c: bf16 convert of w_in ----------------
__global__ void __launch_bounds__(256) k_splitw(const float* __restrict__ w){
    int i = blockIdx.x*256 + threadIdx.x;
    float4 v0 = ((const float4*)w)[2*i];
    float4 v1 = ((const float4*)w)[2*i+1];
    uint4 H;
    H.x = bf2pack(v0.x, v0.y); H.y = bf2pack(v0.z, v0.w);
    H.z = bf2pack(v1.x, v1.y); H.w = bf2pack(v1.z, v1.w);
    ((uint4*)g_wh)[i] = H;
}

// ---------------- K1: 2x2 max+mean pool of input1 -> (B,N,C) ----------------
__global__ void __launch_bounds__(256) k_pool1(const float* __restrict__ in1){
    __shared__ float tile[64][65];
    int ny = blockIdx.x, c0 = blockIdx.y * 64, b = blockIdx.z;
    int tid = threadIdx.x;
    #pragma unroll
    for (int p = 0; p < 16; p++){
        int l = p*256 + tid;
        int nx = l & 63, cc = l >> 6;
        const float* base = in1 + (((b*CC + c0+cc)*HW + 2*ny)*HW + 2*nx);
        float2 r0 = *(const float2*)base;
        float2 r1 = *(const float2*)(base + HW);
        float m = fmaxf(fmaxf(r0.x, r0.y), fmaxf(r1.x, r1.y));
        float s = (r0.x + r0.y + r1.x + r1.y) * 0.25f;
        tile[cc][nx] = m + s;
    }
    __syncthreads();
    #pragma unroll
    for (int p = 0; p < 16; p++){
        int l = p*256 + tid;
        int c = l & 63, nx = l >> 6;
        g_P1[(b*NN + ny*64 + nx)*CC + c0 + c] = tile[c][nx];
    }
}

// ---------------- K2: mma.sync single-term GEMM + bias + 2x2 pool -> g_P2 ----------------
// CTA: 128 o x 128 px. Warp tile 32x64 (4m x 2n). A = w_in bf16; B = input2 bf16.
// D = Ah*Bh. 3-stage pipeline, 2 CTAs/SM.
#define ASTG 8192
#define BSTG 8192
#define STAGE_SZ (ASTG + BSTG)          // 16384
#define GEMM_SMEM (128*132*4)           // 67584 >= 3*STAGE_SZ

__global__ void __launch_bounds__(256, 2) k_gemm(const float* __restrict__ b_in){
    extern __shared__ char smem[];
    uint32_t sb = smem_u32(smem);
    float* Cs = (float*)smem;

    int tid = threadIdx.x;
    int lane = tid & 31, wid = tid >> 5;
    int wm = wid >> 1, wn = wid & 1;    // 4m x 2n warps
    int bid = blockIdx.x;               // ot fastest for L2 B-reuse
    int ot = bid & 3;
    int xh = (bid >> 2) & 1;
    int ny = (bid >> 3) & 63;
    int b  = bid >> 9;
    int o0 = ot * 128;

    float acc[2][8][4];
    #pragma unroll
    for (int i = 0; i < 2; i++)
        #pragma unroll
        for (int j = 0; j < 8; j++)
            #pragma unroll
            for (int q = 0; q < 4; q++) acc[i][j][q] = 0.f;

    auto load_stage = [&](int kc){
        uint32_t st = sb + (kc % 3)*STAGE_SZ;
        #pragma unroll
        for (int q = 0; q < 2; q++){            // A: 512 x 16B
            int id = q*256 + tid;
            int o = id >> 2, c = id & 3;
            int cs = c ^ ((o >> 1) & 3);
            cp16(st + o*64 + cs*16,
                 g_wh + (o0 + o)*CIN + kc*32 + c*8);
        }
        #pragma unroll
        for (int q = 0; q < 2; q++){            // B: 512 x 16B, rows 256B
            int id = q*256 + tid;
            int k = id >> 4, c = id & 15;
            int cs = c ^ (k & 7);
            int sy = c >> 3, x0 = (c & 7) << 3;
            cp16(st + ASTG + k*256 + cs*16,
                 g_2h + (size_t)(b*CIN + kc*32 + k)*(HW*HW)
                      + (2*ny + sy)*HW + xh*64 + x0);
        }
        CP_COMMIT();
    };

    load_stage(0);
    load_stage(1);

    int l15 = lane & 15, lh = lane >> 4;
    int g2 = lane >> 3;
    int bk_off = (g2 & 1)*8 + (lane & 7);
    int bn_off = (g2 >> 1)*8;

    for (int kc = 0; kc < 8; kc++){
        if (kc < 7) { CP_WAIT(1); } else { CP_WAIT(0); }
        __syncthreads();
        if (kc < 6) load_stage(kc + 2);
        uint32_t st = sb + (kc % 3)*STAGE_SZ;

        #pragma unroll
        for (int ks = 0; ks < 2; ks++){
            uint32_t Ah[2][4];
            #pragma unroll
            for (int mf = 0; mf < 2; mf++){
                int r = wm*32 + mf*16 + l15;
                int c = ks*2 + lh;
                int cs = c ^ ((r >> 1) & 3);
                ldsm4(Ah[mf], st + r*64 + cs*16);
            }
            uint32_t Bh[4][4];
            #pragma unroll
            for (int nf2 = 0; nf2 < 4; nf2++){
                int k = ks*16 + bk_off;
                int n = wn*64 + nf2*16 + bn_off;
                int c = n >> 3;
                int cs = c ^ (k & 7);
                ldsm4t(Bh[nf2], st + ASTG + k*256 + cs*16);
            }
            #pragma unroll
            for (int mf = 0; mf < 2; mf++)
                #pragma unroll
                for (int nf = 0; nf < 8; nf++)
                    mma16816(acc[mf][nf], Ah[mf], &Bh[nf >> 1][(nf & 1)*2]);
        }
        __syncthreads();
    }

    // ---- epilogue: stage C (128 x 132), 2x2 pool (max + mean), +2*bias ----
    #pragma unroll
    for (int mf = 0; mf < 2; mf++)
        #pragma unroll
        for (int nf = 0; nf < 8; nf++){
            int row = wm*32 + mf*16 + (lane >> 2);
            int col = wn*64 + nf*8 + (lane & 3)*2;
            *(float2*)&Cs[row*132 + col]     = make_float2(acc[mf][nf][0], acc[mf][nf][1]);
            *(float2*)&Cs[(row+8)*132 + col] = make_float2(acc[mf][nf][2], acc[mf][nf][3]);
        }
    __syncthreads();

    int pn_base = b*NN + ny*64 + xh*32;
    #pragma unroll
    for (int j = 0; j < 16; j++){
        int idx = j*256 + tid;
        int o = idx & 127, i = idx >> 7;        // pooled px i 0..31
        float2 v0 = *(const float2*)&Cs[o*132 + 2*i];        // sy=0
        float2 v1 = *(const float2*)&Cs[o*132 + 64 + 2*i];   // sy=1
        float m = fmaxf(fmaxf(v0.x, v0.y), fmaxf(v1.x, v1.y));
        float s = (v0.x + v0.y + v1.x + v1.y) * 0.25f;
        g_P2[(pn_base + i)*CC + o0 + o] = m + s + 2.f*b_in[o0 + o];
    }
}

// ---------------- K3: q/k = focus(lrelu(p + pos) / scale) ----------------
__global__ void __launch_bounds__(256) k_focus(const float* __restrict__ pos1,
                                               const float* __restrict__ pos2){
    int warp = threadIdx.x >> 5, lane = threadIdx.x & 31;
    int r = blockIdx.x * 8 + warp;
    int b = r >> 12, n = r & (NN - 1);
    const float* p1 = &g_P1[(b*NN + n)*CC];
    const float* p2 = &g_P2[(b*NN + n)*CC];
    const float* q1 = &pos1[n*CC];
    const float* q2 = &pos2[n*CC];
    float tq3[16], tk3[16];
    float s2q = 0.f, s6q = 0.f, s2k = 0.f, s6k = 0.f;
    #pragma unroll
    for (int i = 0; i < 4; i++){
        int c = i*128 + lane*4;
        float4 a  = *(const float4*)(p1 + c);
        float4 pa = *(const float4*)(q1 + c);
        float4 kk = *(const float4*)(p2 + c);
        float4 pk = *(const float4*)(q2 + c);
        float4 is = *(const float4*)(g_isc + c);
        float ta[4] = { lrelu(a.x + pa.x)*is.x, lrelu(a.y + pa.y)*is.y,
                        lrelu(a.z + pa.z)*is.z, lrelu(a.w + pa.w)*is.w };
        float tb[4] = { lrelu(kk.x + pk.x)*is.x, lrelu(kk.y + pk.y)*is.y,
                        lrelu(kk.z + pk.z)*is.z, lrelu(kk.w + pk.w)*is.w };
        #pragma unroll
        for (int j = 0; j < 4; j++){
            float t2 = ta[j]*ta[j]; float t3 = t2*ta[j];
            s2q += t2; s6q += t3*t3; tq3[i*4+j] = t3;
            float u2 = tb[j]*tb[j]; float u3 = u2*tb[j];
            s2k += u2; s6k += u3*u3; tk3[i*4+j] = u3;
        }
    }
    #pragma unroll
    for (int off = 16; off; off >>= 1){
        s2q += __shfl_xor_sync(0xffffffffu, s2q, off);
        s6q += __shfl_xor_sync(0xffffffffu, s6q, off);
        s2k += __shfl_xor_sync(0xffffffffu, s2k, off);
        s6k += __shfl_xor_sync(0xffffffffu, s6k, off);
    }
    float rq = sqrtf(s2q / s6q);
    float rk = sqrtf(s2k / s6k);
    #pragma unroll
    for (int i = 0; i < 4; i++){
        int c = i*128 + lane*4;
        *(float4*)&g_Q[(b*NN + n)*CC + c] =
            make_float4(rq*tq3[i*4], rq*tq3[i*4+1], rq*tq3[i*4+2], rq*tq3[i*4+3]);
        *(float4*)&g_K[(b*NN + n)*CC + c] =
            make_float4(rk*tk3[i*4], rk*tk3[i*4+1], rk*tk3[i*4+2], rk*tk3[i*4+3]);
    }
}

// ---------------- K4a: partial kv over 1/8 of N, FFMA2 over n-pairs ----------------
__global__ void __launch_bounds__(256) k_kvp(){
    __shared__ ull ks2[32][HD];     // [n2][d], pair = (n even, n odd)
    __shared__ ull vs2[32][HD];
    __shared__ float red[256*16];
    int bh  = blockIdx.x & 127;
    int seg = blockIdx.x >> 7;
    int b = bh >> 4, h = bh & 15;
    int tid = threadIdx.x;
    int g  = tid >> 6;
    int t6 = tid & 63;
    int ty = t6 >> 3, tx = t6 & 7;
    ull acc2[4][4];
    #pragma unroll
    for (int i = 0; i < 4; i++)
        #pragma unroll
        for (int j = 0; j < 4; j++) acc2[i][j] = 0ull;
    const float* Kb = &g_K [(b*NN)*CC + h*HD];
    const float* Vb = &g_P2[(b*NN)*CC + h*HD];
    for (int ch = seg*8; ch < seg*8 + 8; ch++){
        #pragma unroll
        for (int p = 0; p < 8; p++){
            int l = p*256 + tid;
            int d = l & 31, nn = l >> 5;
            ((float*)&ks2[nn>>1][d])[nn&1] = Kb[(ch*64 + nn)*CC + d];
            ((float*)&vs2[nn>>1][d])[nn&1] = Vb[(ch*64 + nn)*CC + d];
        }
        __syncthreads();
        #pragma unroll
        for (int q = 0; q < 8; q++){
            int n2 = g*8 + q;
            ulonglong2 ka = ((const ulonglong2*)&ks2[n2][ty*4])[0];
            ulonglong2 kb = ((const ulonglong2*)&ks2[n2][ty*4])[1];
            ulonglong2 va = ((const ulonglong2*)&vs2[n2][tx*4])[0];
            ulonglong2 vb = ((const ulonglong2*)&vs2[n2][tx*4])[1];
            ull ka2[4] = { ka.x, ka.y, kb.x, kb.y };
            ull va2[4] = { va.x, va.y, vb.x, vb.y };
            #pragma unroll
            for (int i = 0; i < 4; i++)
                #pragma unroll
                for (int j = 0; j < 4; j++)
                    acc2[i][j] = ffma2(ka2[i], va2[j], acc2[i][j]);
        }
        __syncthreads();
    }
    #pragma unroll
    for (int i = 0; i < 4; i++)
        #pragma unroll
        for (int j = 0; j < 4; j++){
            float lo, hi;
            unpack2(acc2[i][j], lo, hi);
            red[tid*16 + i*4 + j] = lo + hi;
        }
    __syncthreads();
    if (tid < 64){
        #pragma unroll
        for (int idx = 0; idx < 16; idx++){
            float s = red[tid*16 + idx] + red[(tid+64)*16 + idx]
                    + red[(tid+128)*16 + idx] + red[(tid+192)*16 + idx];
            int i = idx >> 2, j = idx & 3;
            int d = (tid >> 3)*4 + i, e = (tid & 7)*4 + j;
            g_KVp[(seg*128 + bh)*1024 + d*HD + e] = s;
        }
    }
}

// ---------------- K4b: reduce partials -> g_KV ----------------
__global__ void __launch_bounds__(1024) k_kvr(){
    int bh = blockIdx.x, idx = threadIdx.x;
    float s = 0.f;
    #pragma unroll
    for (int g = 0; g < 8; g++) s += g_KVp[(g*128 + bh)*1024 + idx];
    g_KV[bh*1024 + idx] = s * (1.0f/NN);
}

// ---------------- K5: attn = q@kv + lrelu(v@wv^T + bv), FFMA2 over d ----------------
__global__ void __launch_bounds__(256) k_attn(const float* __restrict__ w_v,
                                              const float* __restrict__ b_v){
    __shared__ float qs [128][HD];
    __shared__ float vsm[128][HD];
    __shared__ float osm[HD][132];
    int bh = blockIdx.x, seg = blockIdx.y;
    int b = bh >> 4, h = bh & 15;
    int tid = threadIdx.x;
    int e = tid & 31, grp = tid >> 5;
    ull kvc2[16], wv2[16];
    #pragma unroll
    for (int d2 = 0; d2 < 16; d2++){
        kvc2[d2] = pack2(g_KV[(bh*HD + 2*d2)*HD + e], g_KV[(bh*HD + 2*d2+1)*HD + e]);
        wv2[d2]  = pack2(w_v[e*HD + 2*d2], w_v[e*HD + 2*d2 + 1]);
    }
    float bve = b_v[e];
    const float* Qb = &g_Q [(b*NN)*CC + h*HD];
    const float* Vb = &g_P2[(b*NN)*CC + h*HD];
    float* Ob = &g_ATT[(b*CC + h*HD)*NN];
    for (int cc = 0; cc < 8; cc++){
        int n0 = seg*1024 + cc*128;
        #pragma unroll
        for (int p = 0; p < 16; p++){
            int l = p*256 + tid;
            int d = l & 31, nn = l >> 5;
            qs [nn][d] = Qb[(n0 + nn)*CC + d];
            vsm[nn][d] = Vb[(n0 + nn)*CC + d];
        }
        __syncthreads();
        #pragma unroll
        for (int q = 0; q < 16; q++){
            int nn = grp*16 + q;
            ull x2 = 0ull, c2 = 0ull;
            #pragma unroll
            for (int d4 = 0; d4 < 8; d4++){
                ulonglong2 qq = ((const ulonglong2*)&qs [nn][0])[d4];
                ulonglong2 vv = ((const ulonglong2*)&vsm[nn][0])[d4];
                x2 = ffma2(qq.x, kvc2[2*d4],   x2);
                x2 = ffma2(qq.y, kvc2[2*d4+1], x2);
                c2 = ffma2(vv.x, wv2[2*d4],    c2);
                c2 = ffma2(vv.y, wv2[2*d4+1],  c2);
            }
            float xl, xh, cl, chh;
            unpack2(x2, xl, xh);
            unpack2(c2, cl, chh);
            osm[e][nn] = (xl + xh) + lrelu((cl + chh) + bve);
        }
        __syncthreads();
        #pragma unroll
        for (int p = 0; p < 16; p++){
            int l = p*256 + tid;
            int nn = l & 127, ee = l >> 7;
            Ob[ee*NN + n0 + nn] = osm[ee][nn];
        }
        __syncthreads();
    }
}

// ---------------- K6: bilinear upsample + sigmoid ----------------
__global__ void __launch_bounds__(256) k_upsample(float* __restrict__ out){
    int x  = threadIdx.x & 127, ys = threadIdx.x >> 7;
    int y  = blockIdx.x*2 + ys;
    int c  = blockIdx.y, b = blockIdx.z;
    const float S = 63.f / 127.f;
    float tyf = (float)y * S; int y0 = (int)tyf; if (y0 > 62) y0 = 62; float wy = tyf - (float)y0;
    float txf = (float)x * S; int x0 = (int)txf; if (x0 > 62) x0 = 62; float wx = txf - (float)x0;
    const float* att = &g_ATT[(b*CC + c)*NN];
    float a00 = att[y0*64 + x0    ], a01 = att[y0*64 + x0 + 1];
    float a10 = att[(y0+1)*64 + x0], a11 = att[(y0+1)*64 + x0 + 1];
    float r0 = a00*(1.f - wx) + a01*wx;
    float r1 = a10*(1.f - wx) + a11*wx;
    float v  = r0*(1.f - wy) + r1*wy;
    out[((b*CC + c)*HW + y)*HW + x] = 1.f / (1.f + expf(-v));
}

// ---------------- launch ----------------
extern "C" void kernel_launch(void* const* d_in, const int* in_sizes, int n_in,
                              void* d_out, int out_size){
    const float* input1 = (const float*)d_in[0];
    const float* input2 = (const float*)d_in[1];
    const float* w_in   = (const float*)d_in[2];
    const float* b_in   = (const float*)d_in[3];
    const float* w_v    = (const float*)d_in[4];
    const float* b_v    = (const float*)d_in[5];
    const float* sparam = (const float*)d_in[6];
    const float* pos1   = (const float*)d_in[7];
    const float* pos2   = (const float*)d_in[8];
    float* out = (float*)d_out;

    cudaFuncSetAttribute(k_gemm, cudaFuncAttributeMaxDynamicSharedMemorySize, GEMM_SMEM);

    // k_gemm stays the 4th launch: the ncu capture window lands there.
    k_scale    <<<1, CC>>>(sparam);
    k_splitw   <<<64, 256>>>(w_in);
    k_split    <<<16384, 256>>>(input2);
    k_gemm     <<<4096, 256, GEMM_SMEM>>>(b_in);
    k_pool1    <<<dim3(64, 8, 8), 256>>>(input1);
    k_focus    <<<4096, 256>>>(pos1, pos2);
    k_kvp      <<<1024, 256>>>();
    k_kvr      <<<128, 1024>>>();
    k_attn     <<<dim3(128, 4), 256>>>(w_v, b_v);
    k_upsample <<<dim3(64, 512, 8), 256>>>(out);
}

// round 17
// speedup vs baseline: 1.4660x; 1.0352x over previous
#include <cuda_runtime.h>
#include <cuda_bf16.h>
#include <stdint.h>
#include <math.h>

#define BB   8
#define CC   512
#define CIN  256
#define HW   128
#define NN   4096
#define NHD  16
#define HD   32

__device__ float g_P1 [BB*NN*CC];
__device__ float g_P2 [BB*NN*CC];
__device__ float g_Q  [BB*NN*CC];
__device__ float g_K  [BB*NN*CC];
__device__ float g_KVp[8*BB*NHD*HD*HD];
__device__ float g_ATT[BB*CC*NN];
__device__ __nv_bfloat16 g_2h[BB*CIN*HW*HW];
__device__ __nv_bfloat16 g_wh[CC*CIN];

__device__ __forceinline__ float lrelu(float x){ return x >= 0.f ? x : 0.1f*x; }

__device__ __forceinline__ uint32_t smem_u32(const void* p){
    uint32_t a;
    asm("{ .reg .u64 t; cvta.to.shared.u64 t, %1; cvt.u32.u64 %0, t; }" : "=r"(a) : "l"(p));
    return a;
}
__device__ __forceinline__ void cp16(uint32_t dst, const void* src){
    asm volatile("cp.async.cg.shared.global [%0], [%1], 16;" :: "r"(dst), "l"(src) : "memory");
}
#define CP_COMMIT()   asm volatile("cp.async.commit_group;" ::: "memory")
#define CP_WAIT(n)    asm volatile("cp.async.wait_group %0;" :: "n"(n) : "memory")

__device__ __forceinline__ void ldsm4(uint32_t* r, uint32_t addr){
    asm volatile("ldmatrix.sync.aligned.m8n8.x4.shared.b16 {%0,%1,%2,%3}, [%4];"
        : "=r"(r[0]), "=r"(r[1]), "=r"(r[2]), "=r"(r[3]) : "r"(addr));
}
__device__ __forceinline__ void ldsm4t(uint32_t* r, uint32_t addr){
    asm volatile("ldmatrix.sync.aligned.m8n8.x4.trans.shared.b16 {%0,%1,%2,%3}, [%4];"
        : "=r"(r[0]), "=r"(r[1]), "=r"(r[2]), "=r"(r[3]) : "r"(addr));
}
__device__ __forceinline__ void mma16816(float* d, const uint32_t* a, const uint32_t* b){
    asm volatile("mma.sync.aligned.m16n8k16.row.col.f32.bf16.bf16.f32 "
        "{%0,%1,%2,%3}, {%4,%5,%6,%7}, {%8,%9}, {%0,%1,%2,%3};"
        : "+f"(d[0]), "+f"(d[1]), "+f"(d[2]), "+f"(d[3])
        : "r"(a[0]), "r"(a[1]), "r"(a[2]), "r"(a[3]), "r"(b[0]), "r"(b[1]));
}
__device__ __forceinline__ uint32_t bf2pack(float x, float y){
    __nv_bfloat162 t; t.x = __float2bfloat16(x); t.y = __float2bfloat16(y);
    return *(uint32_t*)&t;
}

// ---------------- K0b: bf16 convert of input2 ----------------
__global__ void __launch_bounds__(256) k_split(const float* __restrict__ in2){
    int i = blockIdx.x*256 + threadIdx.x;
    float4 v0 = ((const float4*)in2)[2*i];
    float4 v1 = ((const float4*)in2)[2*i+1];
    uint4 H;
    H.x = bf2pack(v0.x, v0.y); H.y = bf2pack(v0.z, v0.w);
    H.z = bf2pack(v1.x, v1.y); H.w = bf2pack(v1.z, v1.w);
    ((uint4*)g_2h)[i] = H;
}

// ---------------- K0c: bf16 convert of w_in ----------------
__global__ void __launch_bounds__(256) k_splitw(const float* __restrict__ w){
    int i = blockIdx.x*256 + threadIdx.x;
    float4 v0 = ((const float4*)w)[2*i];
    float4 v1 = ((const float4*)w)[2*i+1];
    uint4 H;
    H.x = bf2pack(v0.x, v0.y); H.y = bf2pack(v0.z, v0.w);
    H.z = bf2pack(v1.x, v1.y); H.w = bf2pack(v1.z, v1.w);
    ((uint4*)g_wh)[i] = H;
}

// ---------------- K1: 2x2 max+mean pool of input1 -> (B,N,C) ----------------
__global__ void __launch_bounds__(256) k_pool1(const float* __restrict__ in1){
    __shared__ float tile[64][65];
    int ny = blockIdx.x, c0 = blockIdx.y * 64, b = blockIdx.z;
    int tid = threadIdx.x;
    #pragma unroll
    for (int p = 0; p < 16; p++){
        int l = p*256 + tid;
        int nx = l & 63, cc = l >> 6;
        const float* base = in1 + (((b*CC + c0+cc)*HW + 2*ny)*HW + 2*nx);
        float2 r0 = *(const float2*)base;
        float2 r1 = *(const float2*)(base + HW);
        float m = fmaxf(fmaxf(r0.x, r0.y), fmaxf(r1.x, r1.y));
        float s = (r0.x + r0.y + r1.x + r1.y) * 0.25f;
        tile[cc][nx] = m + s;
    }
    __syncthreads();
    #pragma unroll
    for (int p = 0; p < 16; p++){
        int l = p*256 + tid;
        int c = l & 63, nx = l >> 6;
        g_P1[(b*NN + ny*64 + nx)*CC + c0 + c] = tile[c][nx];
    }
}

// ---------------- K2: mma.sync single-term GEMM + bias + 2x2 pool -> g_P2 ----------------
#define ASTG 8192
#define BSTG 8192
#define STAGE_SZ (ASTG + BSTG)          // 16384
#define GEMM_SMEM (128*132*4)           // 67584 >= 3*STAGE_SZ

__global__ void __launch_bounds__(256, 2) k_gemm(const float* __restrict__ b_in){
    extern __shared__ char smem[];
    uint32_t sb = smem_u32(smem);
    float* Cs = (float*)smem;

    int tid = threadIdx.x;
    int lane = tid & 31, wid = tid >> 5;
    int wm = wid >> 1, wn = wid & 1;    // 4m x 2n warps
    int bid = blockIdx.x;               // ot fastest for L2 B-reuse
    int ot = bid & 3;
    int xh = (bid >> 2) & 1;
    int ny = (bid >> 3) & 63;
    int b  = bid >> 9;
    int o0 = ot * 128;

    float acc[2][8][4];
    #pragma unroll
    for (int i = 0; i < 2; i++)
        #pragma unroll
        for (int j = 0; j < 8; j++)
            #pragma unroll
            for (int q = 0; q < 4; q++) acc[i][j][q] = 0.f;

    auto load_stage = [&](int kc){
        uint32_t st = sb + (kc % 3)*STAGE_SZ;
        #pragma unroll
        for (int q = 0; q < 2; q++){            // A: 512 x 16B
            int id = q*256 + tid;
            int o = id >> 2, c = id & 3;
            int cs = c ^ ((o >> 1) & 3);
            cp16(st + o*64 + cs*16,
                 g_wh + (o0 + o)*CIN + kc*32 + c*8);
        }
        #pragma unroll
        for (int q = 0; q < 2; q++){            // B: 512 x 16B, rows 256B
            int id = q*256 + tid;
            int k = id >> 4, c = id & 15;
            int cs = c ^ (k & 7);
            int sy = c >> 3, x0 = (c & 7) << 3;
            cp16(st + ASTG + k*256 + cs*16,
                 g_2h + (size_t)(b*CIN + kc*32 + k)*(HW*HW)
                      + (2*ny + sy)*HW + xh*64 + x0);
        }
        CP_COMMIT();
    };

    load_stage(0);
    load_stage(1);

    int l15 = lane & 15, lh = lane >> 4;
    int g2 = lane >> 3;
    int bk_off = (g2 & 1)*8 + (lane & 7);
    int bn_off = (g2 >> 1)*8;

    for (int kc = 0; kc < 8; kc++){
        if (kc < 7) { CP_WAIT(1); } else { CP_WAIT(0); }
        __syncthreads();
        if (kc < 6) load_stage(kc + 2);
        uint32_t st = sb + (kc % 3)*STAGE_SZ;

        #pragma unroll
        for (int ks = 0; ks < 2; ks++){
            uint32_t Ah[2][4];
            #pragma unroll
            for (int mf = 0; mf < 2; mf++){
                int r = wm*32 + mf*16 + l15;
                int c = ks*2 + lh;
                int cs = c ^ ((r >> 1) & 3);
                ldsm4(Ah[mf], st + r*64 + cs*16);
            }
            uint32_t Bh[4][4];
            #pragma unroll
            for (int nf2 = 0; nf2 < 4; nf2++){
                int k = ks*16 + bk_off;
                int n = wn*64 + nf2*16 + bn_off;
                int c = n >> 3;
                int cs = c ^ (k & 7);
                ldsm4t(Bh[nf2], st + ASTG + k*256 + cs*16);
            }
            #pragma unroll
            for (int mf = 0; mf < 2; mf++)
                #pragma unroll
                for (int nf = 0; nf < 8; nf++)
                    mma16816(acc[mf][nf], Ah[mf], &Bh[nf >> 1][(nf & 1)*2]);
        }
        __syncthreads();
    }

    // ---- epilogue: stage C (128 x 132), 2x2 pool (max + mean), +2*bias ----
    #pragma unroll
    for (int mf = 0; mf < 2; mf++)
        #pragma unroll
        for (int nf = 0; nf < 8; nf++){
            int row = wm*32 + mf*16 + (lane >> 2);
            int col = wn*64 + nf*8 + (lane & 3)*2;
            *(float2*)&Cs[row*132 + col]     = make_float2(acc[mf][nf][0], acc[mf][nf][1]);
            *(float2*)&Cs[(row+8)*132 + col] = make_float2(acc[mf][nf][2], acc[mf][nf][3]);
        }
    __syncthreads();

    int pn_base = b*NN + ny*64 + xh*32;
    #pragma unroll
    for (int j = 0; j < 16; j++){
        int idx = j*256 + tid;
        int o = idx & 127, i = idx >> 7;        // pooled px i 0..31
        float2 v0 = *(const float2*)&Cs[o*132 + 2*i];        // sy=0
        float2 v1 = *(const float2*)&Cs[o*132 + 64 + 2*i];   // sy=1
        float m = fmaxf(fmaxf(v0.x, v0.y), fmaxf(v1.x, v1.y));
        float s = (v0.x + v0.y + v1.x + v1.y) * 0.25f;
        g_P2[(pn_base + i)*CC + o0 + o] = m + s + 2.f*b_in[o0 + o];
    }
}

// ---------------- K3: q/k = focus(lrelu(p + pos) / softplus(scale)) ----------------
__global__ void __launch_bounds__(256) k_focus(const float* __restrict__ pos1,
                                               const float* __restrict__ pos2,
                                               const float* __restrict__ sp){
    int warp = threadIdx.x >> 5, lane = threadIdx.x & 31;
    int r = blockIdx.x * 8 + warp;
    int b = r >> 12, n = r & (NN - 1);
    const float* p1 = &g_P1[(b*NN + n)*CC];
    const float* p2 = &g_P2[(b*NN + n)*CC];
    const float* q1 = &pos1[n*CC];
    const float* q2 = &pos2[n*CC];
    float tq3[16], tk3[16];
    float s2q = 0.f, s6q = 0.f, s2k = 0.f, s6k = 0.f;
    #pragma unroll
    for (int i = 0; i < 4; i++){
        int c = i*128 + lane*4;
        float4 a  = *(const float4*)(p1 + c);
        float4 pa = *(const float4*)(q1 + c);
        float4 kk = *(const float4*)(p2 + c);
        float4 pk = *(const float4*)(q2 + c);
        float4 sv = *(const float4*)(sp + c);
        float4 is;
        is.x = 1.f / ((sv.x > 20.f) ? sv.x : log1pf(expf(sv.x)));
        is.y = 1.f / ((sv.y > 20.f) ? sv.y : log1pf(expf(sv.y)));
        is.z = 1.f / ((sv.z > 20.f) ? sv.z : log1pf(expf(sv.z)));
        is.w = 1.f / ((sv.w > 20.f) ? sv.w : log1pf(expf(sv.w)));
        float ta[4] = { lrelu(a.x + pa.x)*is.x, lrelu(a.y + pa.y)*is.y,
                        lrelu(a.z + pa.z)*is.z, lrelu(a.w + pa.w)*is.w };
        float tb[4] = { lrelu(kk.x + pk.x)*is.x, lrelu(kk.y + pk.y)*is.y,
                        lrelu(kk.z + pk.z)*is.z, lrelu(kk.w + pk.w)*is.w };
        #pragma unroll
        for (int j = 0; j < 4; j++){
            float t2 = ta[j]*ta[j]; float t3 = t2*ta[j];
            s2q += t2; s6q += t3*t3; tq3[i*4+j] = t3;
            float u2 = tb[j]*tb[j]; float u3 = u2*tb[j];
            s2k += u2; s6k += u3*u3; tk3[i*4+j] = u3;
        }
    }
    #pragma unroll
    for (int off = 16; off; off >>= 1){
        s2q += __shfl_xor_sync(0xffffffffu, s2q, off);
        s6q += __shfl_xor_sync(0xffffffffu, s6q, off);
        s2k += __shfl_xor_sync(0xffffffffu, s2k, off);
        s6k += __shfl_xor_sync(0xffffffffu, s6k, off);
    }
    float rq = sqrtf(s2q / s6q);
    float rk = sqrtf(s2k / s6k);
    #pragma unroll
    for (int i = 0; i < 4; i++){
        int c = i*128 + lane*4;
        *(float4*)&g_Q[(b*NN + n)*CC + c] =
            make_float4(rq*tq3[i*4], rq*tq3[i*4+1], rq*tq3[i*4+2], rq*tq3[i*4+3]);
        *(float4*)&g_K[(b*NN + n)*CC + c] =
            make_float4(rk*tk3[i*4], rk*tk3[i*4+1], rk*tk3[i*4+2], rk*tk3[i*4+3]);
    }
}

// ---------------- K4: partial kv over 1/8 of N ----------------
__global__ void __launch_bounds__(256) k_kvp(){
    __shared__ float ks[64][HD];
    __shared__ float vs[64][HD];
    __shared__ float red[256*16];
    int bh  = blockIdx.x & 127;
    int seg = blockIdx.x >> 7;
    int b = bh >> 4, h = bh & 15;
    int tid = threadIdx.x;
    int g  = tid >> 6;
    int t6 = tid & 63;
    int ty = t6 >> 3, tx = t6 & 7;
    float acc[4][4] = {};
    const float* Kb = &g_K [(b*NN)*CC + h*HD];
    const float* Vb = &g_P2[(b*NN)*CC + h*HD];
    for (int ch = seg*8; ch < seg*8 + 8; ch++){
        #pragma unroll
        for (int p = 0; p < 8; p++){
            int l = p*256 + tid;
            int d = l & 31, nn = l >> 5;
            ks[nn][d] = Kb[(ch*64 + nn)*CC + d];
            vs[nn][d] = Vb[(ch*64 + nn)*CC + d];
        }
        __syncthreads();
        #pragma unroll
        for (int q = 0; q < 16; q++){
            int n = g*16 + q;
            float4 kk = *(const float4*)&ks[n][ty*4];
            float4 vv = *(const float4*)&vs[n][tx*4];
            float ka[4] = {kk.x, kk.y, kk.z, kk.w};
            float va[4] = {vv.x, vv.y, vv.z, vv.w};
            #pragma unroll
            for (int i = 0; i < 4; i++)
                #pragma unroll
                for (int j = 0; j < 4; j++) acc[i][j] += ka[i]*va[j];
        }
        __syncthreads();
    }
    #pragma unroll
    for (int i = 0; i < 4; i++)
        #pragma unroll
        for (int j = 0; j < 4; j++) red[tid*16 + i*4 + j] = acc[i][j];
    __syncthreads();
    if (tid < 64){
        #pragma unroll
        for (int idx = 0; idx < 16; idx++){
            float s = red[tid*16 + idx] + red[(tid+64)*16 + idx]
                    + red[(tid+128)*16 + idx] + red[(tid+192)*16 + idx];
            int i = idx >> 2, j = idx & 3;
            int d = (tid >> 3)*4 + i, e = (tid & 7)*4 + j;
            g_KVp[(seg*128 + bh)*1024 + d*HD + e] = s;
        }
    }
}

// ---------------- K5: attn (inline kv reduce) -> (B,C,N) ----------------
__global__ void __launch_bounds__(256) k_attn(const float* __restrict__ w_v,
                                              const float* __restrict__ b_v){
    __shared__ float qs [128][HD];
    __shared__ float vsm[128][HD];
    __shared__ float osm[HD][132];
    int bh = blockIdx.x, seg = blockIdx.y;
    int b = bh >> 4, h = bh & 15;
    int tid = threadIdx.x;
    int e = tid & 31, grp = tid >> 5;
    float kvc[32], wv[32];
    #pragma unroll
    for (int d = 0; d < 32; d++){
        float s = 0.f;
        #pragma unroll
        for (int g = 0; g < 8; g++)
            s += g_KVp[(g*128 + bh)*1024 + d*HD + e];
        kvc[d] = s * (1.0f/NN);
        wv[d]  = w_v[e*HD + d];
    }
    float bve = b_v[e];
    const float* Qb = &g_Q [(b*NN)*CC + h*HD];
    const float* Vb = &g_P2[(b*NN)*CC + h*HD];
    float* Ob = &g_ATT[(b*CC + h*HD)*NN];
    for (int cc = 0; cc < 8; cc++){
        int n0 = seg*1024 + cc*128;
        #pragma unroll
        for (int p = 0; p < 16; p++){
            int l = p*256 + tid;
            int d = l & 31, nn = l >> 5;
            qs [nn][d] = Qb[(n0 + nn)*CC + d];
            vsm[nn][d] = Vb[(n0 + nn)*CC + d];
        }
        __syncthreads();
        #pragma unroll
        for (int q = 0; q < 16; q++){
            int nn = grp*16 + q;
            float x = 0.f, vc = 0.f;
            #pragma unroll
            for (int d4 = 0; d4 < 8; d4++){
                float4 qv = *(const float4*)&qs [nn][d4*4];
                float4 vv = *(const float4*)&vsm[nn][d4*4];
                x  += qv.x*kvc[d4*4] + qv.y*kvc[d4*4+1] + qv.z*kvc[d4*4+2] + qv.w*kvc[d4*4+3];
                vc += vv.x*wv [d4*4] + vv.y*wv [d4*4+1] + vv.z*wv [d4*4+2] + vv.w*wv [d4*4+3];
            }
            osm[e][nn] = x + lrelu(vc + bve);
        }
        __syncthreads();
        #pragma unroll
        for (int p = 0; p < 16; p++){
            int l = p*256 + tid;
            int nn = l & 127, ee = l >> 7;
            Ob[ee*NN + n0 + nn] = osm[ee][nn];
        }
        __syncthreads();
    }
}

// ---------------- K6: bilinear upsample + sigmoid ----------------
__global__ void __launch_bounds__(256) k_upsample(float* __restrict__ out){
    int x  = threadIdx.x & 127, ys = threadIdx.x >> 7;
    int y  = blockIdx.x*2 + ys;
    int c  = blockIdx.y, b = blockIdx.z;
    const float S = 63.f / 127.f;
    float tyf = (float)y * S; int y0 = (int)tyf; if (y0 > 62) y0 = 62; float wy = tyf - (float)y0;
    float txf = (float)x * S; int x0 = (int)txf; if (x0 > 62) x0 = 62; float wx = txf - (float)x0;
    const float* att = &g_ATT[(b*CC + c)*NN];
    float a00 = att[y0*64 + x0    ], a01 = att[y0*64 + x0 + 1];
    float a10 = att[(y0+1)*64 + x0], a11 = att[(y0+1)*64 + x0 + 1];
    float r0 = a00*(1.f - wx) + a01*wx;
    float r1 = a10*(1.f - wx) + a11*wx;
    float v  = r0*(1.f - wy) + r1*wy;
    out[((b*CC + c)*HW + y)*HW + x] = 1.f / (1.f + expf(-v));
}

// ---------------- launch ----------------
extern "C" void kernel_launch(void* const* d_in, const int* in_sizes, int n_in,
                              void* d_out, int out_size){
    const float* input1 = (const float*)d_in[0];
    const float* input2 = (const float*)d_in[1];
    const float* w_in   = (const float*)d_in[2];
    const float* b_in   = (const float*)d_in[3];
    const float* w_v    = (const float*)d_in[4];
    const float* b_v    = (const float*)d_in[5];
    const float* sparam = (const float*)d_in[6];
    const float* pos1   = (const float*)d_in[7];
    const float* pos2   = (const float*)d_in[8];
    float* out = (float*)d_out;

    cudaFuncSetAttribute(k_gemm, cudaFuncAttributeMaxDynamicSharedMemorySize, GEMM_SMEM);

    // k_gemm stays the 4th launch: the ncu capture window lands there.
    k_splitw   <<<64, 256>>>(w_in);
    k_split    <<<16384, 256>>>(input2);
    k_pool1    <<<dim3(64, 8, 8), 256>>>(input1);
    k_gemm     <<<4096, 256, GEMM_SMEM>>>(b_in);
    k_focus    <<<4096, 256>>>(pos1, pos2, sparam);
    k_kvp      <<<1024, 256>>>();
    k_attn     <<<dim3(128, 4), 256>>>(w_v, b_v);
    k_upsample <<<dim3(64, 512, 8), 256>>>(out);
}